// round 12
// baseline (speedup 1.0000x reference)
#include <cuda_runtime.h>
#include <cuda_bf16.h>
#include <math.h>
#include <stdint.h>

// ---------------- problem constants ----------------
#define SEQL  64
#define BATCH 64
#define HID   1024
#define EMBD  1024
#define VOCAB 32000
#define BH    (BATCH*HID)            // 65536
#define LOGITS_N ((size_t)SEQL*BATCH*VOCAB)
#define SQRTE 32.0f
#define HH    (HID*HID)
#define NCTA  256                    // persistent grid, 2 CTAs/SM

// output jobs: 64x64 logits tiles, grouped in t-octets for gW L2 reuse
#define OJOBS     32000u             // 64 t * 500 ntiles
#define OJ_PER_TQ 4000u              // 500 * 8

typedef unsigned long long u64;

__device__ __forceinline__ float sigmf(float x){ return 1.0f/(1.0f + expf(-x)); }

// ---------------- smem / async-copy / mma helpers ----------------
__device__ __forceinline__ uint32_t smem_u32(const void* p){
    uint32_t a;
    asm("{ .reg .u64 t; cvta.to.shared.u64 t, %1; cvt.u32.u64 %0, t; }" : "=r"(a) : "l"(p));
    return a;
}
#define CP16(sa, gp) \
    asm volatile("cp.async.cg.shared.global [%0], [%1], 16;" :: "r"((uint32_t)(sa)), "l"(gp) : "memory")
#define CP_COMMIT() asm volatile("cp.async.commit_group;" ::: "memory")
#define CP_WAIT(n)  asm volatile("cp.async.wait_group %0;" :: "n"(n) : "memory")
#define BARX(id)    asm volatile("bar.sync %0, 128;" :: "r"(id) : "memory")

__device__ __forceinline__ void ldsm4(uint32_t* r, uint32_t addr){
    asm volatile("ldmatrix.sync.aligned.m8n8.x4.shared.b16 {%0,%1,%2,%3}, [%4];"
        : "=r"(r[0]), "=r"(r[1]), "=r"(r[2]), "=r"(r[3]) : "r"(addr));
}
__device__ __forceinline__ void mma_bf16(float* d, const uint32_t* a, const uint32_t* b){
    asm volatile(
        "mma.sync.aligned.m16n8k16.row.col.f32.bf16.bf16.f32 "
        "{%0,%1,%2,%3}, {%4,%5,%6,%7}, {%8,%9}, {%0,%1,%2,%3};"
        : "+f"(d[0]), "+f"(d[1]), "+f"(d[2]), "+f"(d[3])
        : "r"(a[0]), "r"(a[1]), "r"(a[2]), "r"(a[3]), "r"(b[0]), "r"(b[1]));
}

// ---------------- device scratch ----------------
__device__ __align__(16) float g_Xin[SEQL*BH];
__device__ __align__(16) float g_prev0[BH];
__device__ __align__(16) float g_prev1[BH];
__device__ __align__(16) float g_z0[BH];
__device__ __align__(16) float g_z1[BH];
__device__ __align__(16) float g_part[32*BH];
// bf16 hi/lo activation operands
__device__ __align__(16) __nv_bfloat16 b_prev0_h[BH], b_prev0_l[BH];
__device__ __align__(16) __nv_bfloat16 b_prev1_h[BH], b_prev1_l[BH];
__device__ __align__(16) __nv_bfloat16 b_rp0_h[BH],   b_rp0_l[BH];
__device__ __align__(16) __nv_bfloat16 b_rp1_h[BH],   b_rp1_l[BH];
__device__ __align__(16) __nv_bfloat16 b_r0pre_h[BH], b_r0pre_l[BH];
__device__ __align__(16) __nv_bfloat16 b_f0pre_h[BH], b_f0pre_l[BH];
__device__ __align__(16) __nv_bfloat16 b_h0pre_h[BH], b_h0pre_l[BH];
// recurrence weights: 0=Ur0 1=Uf0 2=Uh0 3=Wr1 4=Ur1 5=Wf1 6=Uf1 7=Wh1 8=Uh1
__device__ __align__(16) __nv_bfloat16 gRW_hi[9*HH], gRW_lo[9*HH];
// k_xin operands
__device__ __align__(16) __nv_bfloat16 gX_hi[SEQL*BH], gX_lo[SEQL*BH];
__device__ __align__(16) __nv_bfloat16 gWin_hi[HH], gWin_lo[HH];
// output GEMM operands
__device__ __align__(16) __nv_bfloat16 gH_hi[SEQL*BH], gH_lo[SEQL*BH];
__device__ __align__(16) __nv_bfloat16 gW_hi[(size_t)VOCAB*HID], gW_lo[(size_t)VOCAB*HID];

// persistent-kernel coordination (all monotone -> graph-replay safe)
__device__ unsigned g_barCnt = 0;
__device__ volatile unsigned g_barGen = 0;
__device__ unsigned g_tdone  = 0;    // monotone count of finished timesteps
__device__ unsigned g_jobCtr = 0;    // monotone output-job claim counter

// grid barrier over the 128 rec threads of each CTA (tid 0..127)
__device__ __forceinline__ void gridbar(){
    __threadfence();
    BARX(1);
    if (threadIdx.x == 0){
        unsigned g = g_barGen;
        if (atomicAdd(&g_barCnt, 1u) == NCTA - 1u){
            g_barCnt = 0;
            __threadfence();
            g_barGen = g + 1u;
        } else {
            while (g_barGen == g) { __nanosleep(32); }
        }
        __threadfence();
    }
    BARX(1);
}

__device__ __forceinline__ void split_store(__nv_bfloat16* hi, __nv_bfloat16* lo, size_t i, float v){
    __nv_bfloat16 h = __float2bfloat16_rn(v);
    hi[i] = h;
    lo[i] = __float2bfloat16_rn(v - __bfloat162float(h));
}
__device__ __forceinline__ void split_store4(__nv_bfloat16* hi, __nv_bfloat16* lo, size_t i, float4 v){
    __nv_bfloat162 h0 = __floats2bfloat162_rn(v.x, v.y);
    __nv_bfloat162 h1 = __floats2bfloat162_rn(v.z, v.w);
    __nv_bfloat162 l0 = __floats2bfloat162_rn(v.x - __low2float(h0),  v.y - __high2float(h0));
    __nv_bfloat162 l1 = __floats2bfloat162_rn(v.z - __low2float(h1),  v.w - __high2float(h1));
    *(__nv_bfloat162*)(hi + i)     = h0;
    *(__nv_bfloat162*)(hi + i + 2) = h1;
    *(__nv_bfloat162*)(lo + i)     = l0;
    *(__nv_bfloat162*)(lo + i + 2) = l1;
}
#define V4ADD(a,b) do{ (a).x+=(b).x; (a).y+=(b).y; (a).z+=(b).z; (a).w+=(b).w; }while(0)

// ---------------- standalone 128x128 HMMA kernel (used for Xin only) ----------------
#define OSTAGE 40960
#define OSMEM  (2*OSTAGE)
#define OKIT   (HID/32)

__global__ void __launch_bounds__(256,1) k_mma128(
    const __nv_bfloat16* __restrict__ Ah, const __nv_bfloat16* __restrict__ Al,
    const __nv_bfloat16* __restrict__ Bh, const __nv_bfloat16* __restrict__ Bl,
    float* __restrict__ C, size_t ldc, const float* __restrict__ bias)
{
    extern __shared__ __align__(128) char smem[];
    const uint32_t sb = smem_u32(smem);
    const int tid  = threadIdx.x;
    const int lane = tid & 31;
    const int wid  = tid >> 5;
    const int wm   = wid >> 2;
    const int wn   = wid & 3;
    const int m0 = blockIdx.x * 128;
    const int n0 = blockIdx.y * 128;

    const int rowg = tid >> 2;
    const int seg  = tid & 3;
    const uint32_t soff = (uint32_t)rowg*80 + seg*16;
    const __nv_bfloat16* pAh = Ah + (size_t)(m0 + rowg)*HID + seg*8;
    const __nv_bfloat16* pAl = Al + (size_t)(m0 + rowg)*HID + seg*8;
    const __nv_bfloat16* pBh = Bh + (size_t)(n0 + rowg)*HID + seg*8;
    const __nv_bfloat16* pBl = Bl + (size_t)(n0 + rowg)*HID + seg*8;
    const size_t rstep = (size_t)64*HID;

    auto issue = [&](int buf, int k0){
        uint32_t s0 = sb + buf*OSTAGE;
        CP16(s0 +         soff,         pAh + k0);
        CP16(s0 +         soff + 64*80, pAh + k0 + rstep);
        CP16(s0 + 10240 + soff,         pAl + k0);
        CP16(s0 + 10240 + soff + 64*80, pAl + k0 + rstep);
        CP16(s0 + 20480 + soff,         pBh + k0);
        CP16(s0 + 20480 + soff + 64*80, pBh + k0 + rstep);
        CP16(s0 + 30720 + soff,         pBl + k0);
        CP16(s0 + 30720 + soff + 64*80, pBl + k0 + rstep);
    };

    const int rowA = (lane & 7) + ((lane >> 3) & 1)*8;
    const uint32_t aoff = (uint32_t)(wm*64 + rowA)*80 + (uint32_t)(lane >> 4)*16;
    const int rowB = (lane & 7) + (lane >> 4)*8;
    const uint32_t boff = 20480u + (uint32_t)(wn*32 + rowB)*80 + (uint32_t)((lane >> 3) & 1)*16;

    float acc[4][4][4];
#pragma unroll
    for (int mi = 0; mi < 4; mi++)
#pragma unroll
        for (int ni = 0; ni < 4; ni++)
#pragma unroll
            for (int r = 0; r < 4; r++) acc[mi][ni][r] = 0.f;

    issue(0, 0);
    CP_COMMIT();

    for (int s = 0; s < OKIT; s++){
        if (s + 1 < OKIT){ issue((s+1)&1, (s+1)*32); CP_COMMIT(); CP_WAIT(1); }
        else CP_WAIT(0);
        __syncthreads();

        const uint32_t st = sb + (s&1)*OSTAGE;
#pragma unroll
        for (int kk = 0; kk < 2; kk++){
            uint32_t aH[4][4], aL[4][4], bH[4][2], bL[4][2];
#pragma unroll
            for (int mi = 0; mi < 4; mi++){
                ldsm4(aH[mi], st +         aoff + mi*(16*80) + kk*32);
                ldsm4(aL[mi], st + 10240 + aoff + mi*(16*80) + kk*32);
            }
#pragma unroll
            for (int p = 0; p < 2; p++){
                uint32_t t[4];
                ldsm4(t, st +         boff + p*(16*80) + kk*32);
                bH[2*p][0]=t[0]; bH[2*p][1]=t[1]; bH[2*p+1][0]=t[2]; bH[2*p+1][1]=t[3];
                ldsm4(t, st + 10240 + boff + p*(16*80) + kk*32);
                bL[2*p][0]=t[0]; bL[2*p][1]=t[1]; bL[2*p+1][0]=t[2]; bL[2*p+1][1]=t[3];
            }
#pragma unroll
            for (int mi = 0; mi < 4; mi++)
#pragma unroll
                for (int ni = 0; ni < 4; ni++){
                    mma_bf16(acc[mi][ni], aH[mi], bH[ni]);
                    mma_bf16(acc[mi][ni], aH[mi], bL[ni]);
                    mma_bf16(acc[mi][ni], aL[mi], bH[ni]);
                }
        }
        __syncthreads();
    }

    const int mBase = m0 + wm*64 + (lane >> 2);
    const int nBase = n0 + wn*32 + (lane & 3)*2;
    float2 bv[4];
#pragma unroll
    for (int ni = 0; ni < 4; ni++)
        bv[ni] = bias ? *(const float2*)&bias[nBase + ni*8] : make_float2(0.f, 0.f);
#pragma unroll
    for (int mi = 0; mi < 4; mi++)
#pragma unroll
        for (int ni = 0; ni < 4; ni++)
#pragma unroll
            for (int r = 0; r < 2; r++){
                int m = mBase + mi*16 + r*8;
                float2 v = make_float2(acc[mi][ni][2*r] + bv[ni].x,
                                       acc[mi][ni][2*r+1] + bv[ni].y);
                *(float2*)&C[(size_t)m*ldc + nBase + ni*8] = v;
            }
}

// ---------------- recurrence HMMA core (64x128, rec warps, named bar 1) ----------------
#define RSTAGE   30720
#define RECSMEM  (2*RSTAGE)                   // 61440
#define OUTSTG   20480
#define OUTSMEM  (2*OUTSTG)                   // 40960
#define TOTSMEM  (RECSMEM + OUTSMEM + 16)     // + claim slots

__device__ __noinline__ void mma_rec_core(
    const __nv_bfloat16* __restrict__ Ah, const __nv_bfloat16* __restrict__ Al,
    const __nv_bfloat16* __restrict__ Bh, const __nv_bfloat16* __restrict__ Bl,
    int k0, int kLen, float* __restrict__ Cp, int n0)
{
    extern __shared__ __align__(128) char smem[];
    const uint32_t sb = smem_u32(smem);
    const int tid  = threadIdx.x;
    const int lane = tid & 31;
    const int wn   = tid >> 5;

    auto issue = [&](int buf, int kofs){
        uint32_t s0 = sb + buf*RSTAGE;
#pragma unroll
        for (int i = 0; i < 2; i++){
            int idx = tid + i*128, row = idx >> 2, sg = idx & 3;
            uint32_t off = (uint32_t)row*80 + sg*16;
            size_t g = (size_t)row*HID + kofs + sg*8;
            CP16(s0 +        off, Ah + g);
            CP16(s0 + 5120 + off, Al + g);
        }
#pragma unroll
        for (int i = 0; i < 4; i++){
            int idx = tid + i*128, row = idx >> 2, sg = idx & 3;
            uint32_t off = (uint32_t)row*80 + sg*16;
            size_t g = (size_t)row*HID + kofs + sg*8;
            CP16(s0 + 10240 + off, Bh + g);
            CP16(s0 + 20480 + off, Bl + g);
        }
    };

    const int rowA = (lane & 7) + ((lane >> 3) & 1)*8;
    const uint32_t aoff = (uint32_t)rowA*80 + (uint32_t)(lane >> 4)*16;
    const int rowB = (lane & 7) + (lane >> 4)*8;
    const uint32_t boff = 10240u + (uint32_t)(wn*32 + rowB)*80 + (uint32_t)((lane >> 3) & 1)*16;

    float acc[4][4][4];
#pragma unroll
    for (int mi = 0; mi < 4; mi++)
#pragma unroll
        for (int ni = 0; ni < 4; ni++)
#pragma unroll
            for (int r = 0; r < 4; r++) acc[mi][ni][r] = 0.f;

    const int nst = kLen >> 5;
    issue(0, k0); CP_COMMIT();

    for (int s = 0; s < nst; s++){
        if (s + 1 < nst){ issue((s+1)&1, k0 + (s+1)*32); CP_COMMIT(); CP_WAIT(1); }
        else CP_WAIT(0);
        BARX(1);

        const uint32_t st = sb + (s&1)*RSTAGE;
#pragma unroll
        for (int kk = 0; kk < 2; kk++){
            uint32_t aH[4][4], aL[4][4], bH[4][2], bL[4][2];
#pragma unroll
            for (int mi = 0; mi < 4; mi++){
                ldsm4(aH[mi], st +        aoff + mi*(16*80) + kk*32);
                ldsm4(aL[mi], st + 5120 + aoff + mi*(16*80) + kk*32);
            }
#pragma unroll
            for (int p = 0; p < 2; p++){
                uint32_t tr[4];
                ldsm4(tr, st +         boff + p*(16*80) + kk*32);
                bH[2*p][0]=tr[0]; bH[2*p][1]=tr[1]; bH[2*p+1][0]=tr[2]; bH[2*p+1][1]=tr[3];
                ldsm4(tr, st + 10240 + boff + p*(16*80) + kk*32);
                bL[2*p][0]=tr[0]; bL[2*p][1]=tr[1]; bL[2*p+1][0]=tr[2]; bL[2*p+1][1]=tr[3];
            }
#pragma unroll
            for (int mi = 0; mi < 4; mi++)
#pragma unroll
                for (int ni = 0; ni < 4; ni++){
                    mma_bf16(acc[mi][ni], aH[mi], bH[ni]);
                    mma_bf16(acc[mi][ni], aH[mi], bL[ni]);
                    mma_bf16(acc[mi][ni], aL[mi], bH[ni]);
                }
        }
        BARX(1);
    }

    const int mBase = lane >> 2;
    const int nBase = n0 + wn*32 + (lane & 3)*2;
#pragma unroll
    for (int mi = 0; mi < 4; mi++)
#pragma unroll
        for (int ni = 0; ni < 4; ni++)
#pragma unroll
            for (int r = 0; r < 2; r++){
                int m = mBase + mi*16 + r*8;
                float2 v = make_float2(acc[mi][ni][2*r], acc[mi][ni][2*r+1]);
                *(float2*)&Cp[(size_t)m*HID + nBase + ni*8] = v;
            }
}

// ---------------- output GEMM core (64x64 logits tile, param named bar) ----------------
__device__ __noinline__ void out64_core(int barid, uint32_t smem_ofs, int t, int nt,
                                        const float* __restrict__ outb,
                                        float* __restrict__ logits, int ltid)
{
    extern __shared__ __align__(128) char smem[];
    const uint32_t sb = smem_u32(smem) + smem_ofs;
    const int lane = ltid & 31;
    const int w    = ltid >> 5;
    const int wm   = w >> 1, wn = w & 1;

    const size_t gA = (size_t)t*64*HID;
    const size_t gB = (size_t)nt*64*HID;

    auto issue = [&](int buf, int k0){
        uint32_t s0 = sb + buf*OUTSTG;
#pragma unroll
        for (int i = 0; i < 2; i++){
            int idx = ltid + i*128, row = idx >> 2, sg = idx & 3;
            uint32_t off = (uint32_t)row*80 + sg*16;
            size_t ga = gA + (size_t)row*HID + k0 + sg*8;
            size_t gb = gB + (size_t)row*HID + k0 + sg*8;
            CP16(s0 +         off, gH_hi + ga);
            CP16(s0 +  5120 + off, gH_lo + ga);
            CP16(s0 + 10240 + off, gW_hi + gb);
            CP16(s0 + 15360 + off, gW_lo + gb);
        }
    };

    const int rowA = (lane & 7) + ((lane >> 3) & 1)*8;
    const uint32_t aoff = (uint32_t)(wm*32 + rowA)*80 + (uint32_t)(lane >> 4)*16;
    const int rowB = (lane & 7) + (lane >> 4)*8;
    const uint32_t boff = 10240u + (uint32_t)(wn*32 + rowB)*80 + (uint32_t)((lane >> 3) & 1)*16;

    float acc[2][4][4];
#pragma unroll
    for (int mi = 0; mi < 2; mi++)
#pragma unroll
        for (int ni = 0; ni < 4; ni++)
#pragma unroll
            for (int r = 0; r < 4; r++) acc[mi][ni][r] = 0.f;

    issue(0, 0); CP_COMMIT();

    for (int s = 0; s < 32; s++){
        if (s + 1 < 32){ issue((s+1)&1, (s+1)*32); CP_COMMIT(); CP_WAIT(1); }
        else CP_WAIT(0);
        BARX(barid);

        const uint32_t st = sb + (s&1)*OUTSTG;
#pragma unroll
        for (int kk = 0; kk < 2; kk++){
            uint32_t aH[2][4], aL[2][4], bH[4][2], bL[4][2];
#pragma unroll
            for (int mi = 0; mi < 2; mi++){
                ldsm4(aH[mi], st +        aoff + mi*(16*80) + kk*32);
                ldsm4(aL[mi], st + 5120 + aoff + mi*(16*80) + kk*32);
            }
#pragma unroll
            for (int p = 0; p < 2; p++){
                uint32_t tr[4];
                ldsm4(tr, st +        boff + p*(16*80) + kk*32);
                bH[2*p][0]=tr[0]; bH[2*p][1]=tr[1]; bH[2*p+1][0]=tr[2]; bH[2*p+1][1]=tr[3];
                ldsm4(tr, st + 5120 + boff + p*(16*80) + kk*32);
                bL[2*p][0]=tr[0]; bL[2*p][1]=tr[1]; bL[2*p+1][0]=tr[2]; bL[2*p+1][1]=tr[3];
            }
#pragma unroll
            for (int mi = 0; mi < 2; mi++)
#pragma unroll
                for (int ni = 0; ni < 4; ni++){
                    mma_bf16(acc[mi][ni], aH[mi], bH[ni]);
                    mma_bf16(acc[mi][ni], aH[mi], bL[ni]);
                    mma_bf16(acc[mi][ni], aL[mi], bH[ni]);
                }
        }
        BARX(barid);
    }

    const int mBase = t*64 + wm*32 + (lane >> 2);
    const int nBase = nt*64 + wn*32 + (lane & 3)*2;
    float2 bv[4];
#pragma unroll
    for (int ni = 0; ni < 4; ni++) bv[ni] = *(const float2*)&outb[nBase + ni*8];
#pragma unroll
    for (int mi = 0; mi < 2; mi++)
#pragma unroll
        for (int ni = 0; ni < 4; ni++)
#pragma unroll
            for (int r = 0; r < 2; r++){
                int m = mBase + mi*16 + r*8;
                float2 v = make_float2(acc[mi][ni][2*r] + bv[ni].x,
                                       acc[mi][ni][2*r+1] + bv[ni].y);
                *(float2*)&logits[(size_t)m*VOCAB + nBase + ni*8] = v;
            }
}

// output worker: claim jobs, wait for readiness, compute
__device__ void out_worker(int barid, uint32_t smem_ofs, uint32_t claim_ofs,
                           unsigned jobs_base, unsigned tdone_base,
                           const float* __restrict__ outb, float* __restrict__ logits,
                           int ltid)
{
    extern __shared__ __align__(128) char smem[];
    unsigned* claim = (unsigned*)(smem + claim_ofs);
    for (;;){
        if (ltid == 0) *claim = atomicAdd(&g_jobCtr, 1u) - jobs_base;
        BARX(barid);
        unsigned j = *claim;
        if (j >= OJOBS) break;
        unsigned tq = j / OJ_PER_TQ;
        unsigned rem = j - tq*OJ_PER_TQ;
        unsigned nt = rem >> 3;
        unsigned t  = tq*8u + (rem & 7u);
        if (ltid == 0){
            while (*(volatile unsigned*)&g_tdone < tdone_base + t + 1u) __nanosleep(64);
        }
        BARX(barid);
        out64_core(barid, smem_ofs, (int)t, (int)nt, outb, logits, ltid);
    }
}

// recurrence job bodies -----------------------------------------------------
__device__ __forceinline__ void gates0_body(int nt, int gate, int ks){
    size_t wofs = (size_t)gate*HH + (size_t)nt*128*HID;
    mma_rec_core(b_prev0_h, b_prev0_l, gRW_hi + wofs, gRW_lo + wofs,
                 ks*128, 128, g_part + (size_t)(16 + gate*8 + ks)*BH, nt*128);
}
__device__ __forceinline__ void last_body(int nt, int ks){
    const __nv_bfloat16 *Ah, *Al; int widx, k0;
    if (ks < 8){ Ah = b_h0pre_h; Al = b_h0pre_l; widx = 7; k0 = ks*128; }
    else       { Ah = b_rp1_h;   Al = b_rp1_l;   widx = 8; k0 = (ks-8)*128; }
    size_t wofs = (size_t)widx*HH + (size_t)nt*128*HID;
    mma_rec_core(Ah, Al, gRW_hi + wofs, gRW_lo + wofs,
                 k0, 128, g_part + (size_t)ks*BH, nt*128);
}
__device__ __forceinline__ void mid_job(int j){
    int job = j >> 6;
    int r   = j & 63;
    int nt  = r & 7;
    int ks  = r >> 3;
    const __nv_bfloat16 *Ah, *Al; int widx, k0, kLen;
    if (job == 0){ Ah = b_rp0_h; Al = b_rp0_l; widx = 2; k0 = ks*128; kLen = 128; }
    else {
        int wW = (job == 1) ? 3 : 5;
        int wU = (job == 1) ? 4 : 6;
        if (ks < 4){
            Ah = (job == 1) ? b_r0pre_h : b_f0pre_h;
            Al = (job == 1) ? b_r0pre_l : b_f0pre_l;
            widx = wW; k0 = ks*256;
        } else {
            Ah = b_prev1_h; Al = b_prev1_l;
            widx = wU; k0 = (ks-4)*256;
        }
        kLen = 256;
    }
    size_t wofs = (size_t)widx*HH + (size_t)nt*128*HID;
    mma_rec_core(Ah, Al, gRW_hi + wofs, gRW_lo + wofs,
                 k0, kLen, g_part + (size_t)(job*8 + ks)*BH, nt*128);
}

// fin device functions (1 float4 item per active thread; __ldcg bypasses stale L1)
__device__ __forceinline__ void fin0_one(size_t i, int t,
                                         const float* br0, const float* bf0){
    int n = (int)(i & (HID-1));
    float4 s0 = make_float4(0,0,0,0), s1 = s0;
#pragma unroll
    for (int ks = 0; ks < 8; ks++){
        float4 a = __ldcg((const float4*)&g_part[(size_t)(16+ks)*BH + i]); V4ADD(s0, a);
        float4 b = __ldcg((const float4*)&g_part[(size_t)(24+ks)*BH + i]); V4ADD(s1, b);
    }
    float4 xv = __ldcg((const float4*)&g_Xin[(size_t)t*BH + i]);
    float4 bR = *(const float4*)&br0[n];
    float4 bF = *(const float4*)&bf0[n];
    float4 p0 = __ldcg((const float4*)&g_prev0[i]);
    float4 rp = make_float4(xv.x+bR.x+s0.x, xv.y+bR.y+s0.y, xv.z+bR.z+s0.z, xv.w+bR.w+s0.w);
    float4 fp = make_float4(xv.x+bF.x+s1.x, xv.y+bF.y+s1.y, xv.z+bF.z+s1.z, xv.w+bF.w+s1.w);
    split_store4(b_r0pre_h, b_r0pre_l, i, rp);
    split_store4(b_f0pre_h, b_f0pre_l, i, fp);
    float4 rpv = make_float4(sigmf(rp.x)*p0.x, sigmf(rp.y)*p0.y, sigmf(rp.z)*p0.z, sigmf(rp.w)*p0.w);
    split_store4(b_rp0_h, b_rp0_l, i, rpv);
    *(float4*)&g_z0[i] = make_float4(sigmf(fp.x), sigmf(fp.y), sigmf(fp.z), sigmf(fp.w));
}

__device__ __forceinline__ void fin_mid_one(size_t i, int t, const float* bh0,
                                            const float* br1, const float* bf1){
    int n = (int)(i & (HID-1));
    float4 s0 = make_float4(0,0,0,0), s1 = s0, s2 = s0;
#pragma unroll
    for (int ks = 0; ks < 8; ks++){
        float4 a = __ldcg((const float4*)&g_part[(size_t)ks*BH + i]);      V4ADD(s0, a);
        float4 b = __ldcg((const float4*)&g_part[(size_t)(8+ks)*BH + i]);  V4ADD(s1, b);
        float4 c = __ldcg((const float4*)&g_part[(size_t)(16+ks)*BH + i]); V4ADD(s2, c);
    }
    float4 xv = __ldcg((const float4*)&g_Xin[(size_t)t*BH + i]);
    float4 bH = *(const float4*)&bh0[n];
    float4 ht = make_float4(xv.x+bH.x+s0.x, xv.y+bH.y+s0.y, xv.z+bH.z+s0.z, xv.w+bH.w+s0.w);
    float4 z  = __ldcg((const float4*)&g_z0[i]);
    float4 p0 = __ldcg((const float4*)&g_prev0[i]);
    float4 h0 = make_float4((1.f-z.x)*p0.x + z.x*tanhf(ht.x),
                            (1.f-z.y)*p0.y + z.y*tanhf(ht.y),
                            (1.f-z.z)*p0.z + z.z*tanhf(ht.z),
                            (1.f-z.w)*p0.w + z.w*tanhf(ht.w));
    *(float4*)&g_prev0[i] = h0;
    split_store4(b_prev0_h, b_prev0_l, i, h0);
    split_store4(b_h0pre_h, b_h0pre_l, i, ht);
    float4 bR = *(const float4*)&br1[n];
    float4 bF = *(const float4*)&bf1[n];
    float4 p1 = __ldcg((const float4*)&g_prev1[i]);
    float4 rp1 = make_float4(sigmf(s1.x+bR.x)*p1.x, sigmf(s1.y+bR.y)*p1.y,
                             sigmf(s1.z+bR.z)*p1.z, sigmf(s1.w+bR.w)*p1.w);
    split_store4(b_rp1_h, b_rp1_l, i, rp1);
    *(float4*)&g_z1[i] = make_float4(sigmf(s2.x+bF.x), sigmf(s2.y+bF.y),
                                     sigmf(s2.z+bF.z), sigmf(s2.w+bF.w));
}

__device__ __forceinline__ void finB_one(size_t i, int t, int dogates,
                                         const float* bh1, const float* br0, const float* bf0){
    int n = (int)(i & (HID-1));
    float4 s = make_float4(0,0,0,0);
#pragma unroll
    for (int ks = 0; ks < 16; ks++){
        float4 a = __ldcg((const float4*)&g_part[(size_t)ks*BH + i]); V4ADD(s, a);
    }
    float4 bH = *(const float4*)&bh1[n];
    float4 z  = __ldcg((const float4*)&g_z1[i]);
    float4 p1 = __ldcg((const float4*)&g_prev1[i]);
    float4 h1 = make_float4((1.f-z.x)*p1.x + z.x*tanhf(s.x+bH.x),
                            (1.f-z.y)*p1.y + z.y*tanhf(s.y+bH.y),
                            (1.f-z.z)*p1.z + z.z*tanhf(s.z+bH.z),
                            (1.f-z.w)*p1.w + z.w*tanhf(s.w+bH.w));
    *(float4*)&g_prev1[i] = h1;
    split_store4(b_prev1_h, b_prev1_l, i, h1);
    split_store4(gH_hi, gH_lo, (size_t)t*BH + i, h1);
    if (dogates){
        float4 s0 = make_float4(0,0,0,0), s1 = s0;
#pragma unroll
        for (int ks = 0; ks < 8; ks++){
            float4 a = __ldcg((const float4*)&g_part[(size_t)(16+ks)*BH + i]); V4ADD(s0, a);
            float4 b = __ldcg((const float4*)&g_part[(size_t)(24+ks)*BH + i]); V4ADD(s1, b);
        }
        float4 xv = __ldcg((const float4*)&g_Xin[(size_t)(t+1)*BH + i]);
        float4 bR = *(const float4*)&br0[n];
        float4 bF = *(const float4*)&bf0[n];
        float4 p0 = __ldcg((const float4*)&g_prev0[i]);
        float4 rp = make_float4(xv.x+bR.x+s0.x, xv.y+bR.y+s0.y, xv.z+bR.z+s0.z, xv.w+bR.w+s0.w);
        float4 fp = make_float4(xv.x+bF.x+s1.x, xv.y+bF.y+s1.y, xv.z+bF.z+s1.z, xv.w+bF.w+s1.w);
        split_store4(b_r0pre_h, b_r0pre_l, i, rp);
        split_store4(b_f0pre_h, b_f0pre_l, i, fp);
        float4 rpv = make_float4(sigmf(rp.x)*p0.x, sigmf(rp.y)*p0.y, sigmf(rp.z)*p0.z, sigmf(rp.w)*p0.w);
        split_store4(b_rp0_h, b_rp0_l, i, rpv);
        *(float4*)&g_z0[i] = make_float4(sigmf(fp.x), sigmf(fp.y), sigmf(fp.z), sigmf(fp.w));
    }
}

// ---------------- fused persistent kernel: recurrence + output GEMM ----------------
__global__ void __launch_bounds__(256,2) k_recur(
    const float* __restrict__ br0, const float* __restrict__ bf0,
    const float* __restrict__ bh0, const float* __restrict__ br1,
    const float* __restrict__ bf1, const float* __restrict__ bh1,
    const float* __restrict__ outb, float* __restrict__ logits)
{
    const int b   = blockIdx.x;
    const int tid = threadIdx.x;

    // per-invocation bases (previous invocation fully finished -> stable)
    unsigned tdone_base = *(volatile unsigned*)&g_tdone;
    unsigned jobs_base  = *(volatile unsigned*)&g_jobCtr;

    // entry rendezvous: ALL CTAs read bases before ANY claims/increments
    __syncthreads();
    if (tid == 0){
        unsigned g = g_barGen;
        if (atomicAdd(&g_barCnt, 1u) == NCTA - 1u){
            g_barCnt = 0; __threadfence(); g_barGen = g + 1u;
        } else while (g_barGen == g) __nanosleep(32);
    }
    __syncthreads();

    if (tid >= 128){
        // ---- output warp-group: independent logits-GEMM worker ----
        out_worker(2, RECSMEM, (uint32_t)(RECSMEM + OUTSMEM + 8),
                   jobs_base, tdone_base, outb, logits, tid - 128);
        return;
    }

    // ---- recurrence warp-group (tid 0..127) ----
    const bool finT = (tid < 64);
    const size_t item = ((size_t)b*64 + tid)*4;

    if (b < 128) gates0_body((b>>3)&7, b>>6, b&7);
    gridbar();
    if (finT) fin0_one(item, 0, br0, bf0);
    gridbar();

    for (int t = 0; t < SEQL; t++){
        if (b < 192) mid_job(b);
        gridbar();
        if (finT) fin_mid_one(item, t, bh0, br1, bf1);
        gridbar();
        if (b < 128) last_body(b >> 4, b & 15);
        else if (t < SEQL-1){
            int r = b - 128;
            gates0_body((r>>3)&7, r>>6, r&7);
        }
        gridbar();
        if (finT) finB_one(item, t, (t < SEQL-1) ? 1 : 0, bh1, br0, bf0);
        gridbar();
        if (b == 0 && tid == 0)
            *(volatile unsigned*)&g_tdone = tdone_base + (unsigned)(t + 1);
    }

    // recurrence done: rec warps join the output job pool (rec smem now free)
    out_worker(1, 0u, (uint32_t)(RECSMEM + OUTSMEM),
               jobs_base, tdone_base, outb, logits, tid);
}

// ---------------- conversion kernels ----------------
__global__ void k_init(const float* __restrict__ hid){
    int i = blockIdx.x*blockDim.x + threadIdx.x;
    if (i < BH){
        float v = hid[i];
        g_prev0[i] = v; split_store(b_prev0_h, b_prev0_l, i, v);
    } else {
        int j = i - BH;
        float v = hid[i];
        g_prev1[j] = v; split_store(b_prev1_h, b_prev1_l, j, v);
    }
}

__global__ void k_split(const float* __restrict__ src,
                        __nv_bfloat16* __restrict__ hi, __nv_bfloat16* __restrict__ lo){
    size_t i4 = (size_t)blockIdx.x*blockDim.x + threadIdx.x;
    float4 v = *(const float4*)(src + i4*4);
    split_store4(hi, lo, i4*4, v);
}

__global__ void k_cvtRW(const float* __restrict__ Ur, const float* __restrict__ Uf,
                        const float* __restrict__ Uh, const float* __restrict__ Wr1,
                        const float* __restrict__ Wf1, const float* __restrict__ Wh1){
    const float* srcs[9] = {Ur, Uf, Uh, Wr1, Ur + HH, Wf1, Uf + HH, Wh1, Uh + HH};
    int m = blockIdx.y;
    size_t i4 = (size_t)blockIdx.x*blockDim.x + threadIdx.x;
    float4 v = *(const float4*)(srcs[m] + i4*4);
    split_store4(gRW_hi, gRW_lo, (size_t)m*HH + i4*4, v);
}

__global__ void k_cvtX(const int* __restrict__ toks, const float* __restrict__ emb){
    size_t i4 = (size_t)blockIdx.x*blockDim.x + threadIdx.x;
    int row  = (int)(i4 >> 8);
    int colq = (int)(i4 & 255);
    int tok  = toks[row];
    float4 v = *(const float4*)(emb + (size_t)tok*EMBD + colq*4);
    v.x *= SQRTE; v.y *= SQRTE; v.z *= SQRTE; v.w *= SQRTE;
    split_store4(gX_hi, gX_lo, i4*4, v);
}

__global__ void k_copy(float* __restrict__ dst){
    int i = blockIdx.x*blockDim.x + threadIdx.x;
    dst[i] = (i < BH) ? g_prev0[i] : g_prev1[i - BH];
}

// ---------------- launch ----------------
extern "C" void kernel_launch(void* const* d_in, const int* in_sizes, int n_in,
                              void* d_out, int out_size) {
    const int*   toks = (const int*)  d_in[0];
    const float* hid  = (const float*)d_in[1];
    const float* emb  = (const float*)d_in[2];
    const float* Win  = (const float*)d_in[3];
    const float* Wr1  = (const float*)d_in[4];
    const float* Wf1  = (const float*)d_in[5];
    const float* Wh1  = (const float*)d_in[6];
    const float* Ur   = (const float*)d_in[7];
    const float* br   = (const float*)d_in[8];
    const float* Uf   = (const float*)d_in[9];
    const float* bf   = (const float*)d_in[10];
    const float* Uh   = (const float*)d_in[11];
    const float* bh   = (const float*)d_in[12];
    const float* outW = (const float*)d_in[13];
    const float* outb = (const float*)d_in[14];
    float* out = (float*)d_out;

    const float *br0 = br, *br1 = br + HID;
    const float *bf0 = bf, *bf1 = bf + HID;
    const float *bh0 = bh, *bh1 = bh + HID;

    void *pXh, *pXl, *pWinh, *pWinl, *pWh, *pWl, *pXin;
    cudaGetSymbolAddress(&pXh,  gX_hi);    cudaGetSymbolAddress(&pXl,  gX_lo);
    cudaGetSymbolAddress(&pWinh, gWin_hi); cudaGetSymbolAddress(&pWinl, gWin_lo);
    cudaGetSymbolAddress(&pWh,  gW_hi);    cudaGetSymbolAddress(&pWl,  gW_lo);
    cudaGetSymbolAddress(&pXin, g_Xin);

    cudaFuncSetAttribute(k_mma128, cudaFuncAttributeMaxDynamicSharedMemorySize, OSMEM);
    cudaFuncSetAttribute(k_recur,  cudaFuncAttributeMaxDynamicSharedMemorySize, TOTSMEM);

    k_init<<<2*BH/256, 256>>>(hid);
    k_split<<<((size_t)VOCAB*HID/4)/256, 256>>>(outW, (__nv_bfloat16*)pWh, (__nv_bfloat16*)pWl);
    k_split<<<(HH/4)/256, 256>>>(Win, (__nv_bfloat16*)pWinh, (__nv_bfloat16*)pWinl);
    k_cvtRW<<<dim3(HH/4/256, 9), 256>>>(Ur, Uf, Uh, Wr1, Wf1, Wh1);
    k_cvtX<<<(SEQL*BATCH*EMBD/4)/256, 256>>>(toks, emb);
    // Xin = X @ Win^T  (4096 x 1024)
    k_mma128<<<dim3(32,8), 256, OSMEM>>>((__nv_bfloat16*)pXh, (__nv_bfloat16*)pXl,
                                         (__nv_bfloat16*)pWinh, (__nv_bfloat16*)pWinl,
                                         (float*)pXin, HID, nullptr);

    // fused persistent kernel: recurrence + overlapped output GEMM
    k_recur<<<NCTA, 256, TOTSMEM>>>(br0, bf0, bh0, br1, bf1, bh1, outb, out);

    if ((size_t)out_size >= LOGITS_N + 2*(size_t)BH)
        k_copy<<<2*BH/256, 256>>>(out + LOGITS_N);
}

// round 13
// speedup vs baseline: 1.3005x; 1.3005x over previous
#include <cuda_runtime.h>
#include <cuda_bf16.h>
#include <math.h>
#include <stdint.h>

// ---------------- problem constants ----------------
#define SEQL  64
#define BATCH 64
#define HID   1024
#define EMBD  1024
#define VOCAB 32000
#define BH    (BATCH*HID)            // 65536
#define LOGITS_N ((size_t)SEQL*BATCH*VOCAB)
#define SQRTE 32.0f
#define HH    (HID*HID)
#define NREC  256                    // recurrence CTAs (gridbar group)
#define NTOT  384                    // total persistent CTAs (3/SM x 128 SMs used)

// output jobs: 64x128 logits tiles, t-octet ordering for gW L2 reuse
#define OJOBS     16000u             // 64 t * 250 ntiles
#define OJ_PER_TQ 2000u              // 250 * 8

typedef unsigned long long u64;

__device__ __forceinline__ float sigmf(float x){ return 1.0f/(1.0f + expf(-x)); }

// ---------------- smem / async-copy / mma helpers ----------------
__device__ __forceinline__ uint32_t smem_u32(const void* p){
    uint32_t a;
    asm("{ .reg .u64 t; cvta.to.shared.u64 t, %1; cvt.u32.u64 %0, t; }" : "=r"(a) : "l"(p));
    return a;
}
#define CP16(sa, gp) \
    asm volatile("cp.async.cg.shared.global [%0], [%1], 16;" :: "r"((uint32_t)(sa)), "l"(gp) : "memory")
#define CP_COMMIT() asm volatile("cp.async.commit_group;" ::: "memory")
#define CP_WAIT(n)  asm volatile("cp.async.wait_group %0;" :: "n"(n) : "memory")
#define BARX(id)    asm volatile("bar.sync %0, 128;" :: "r"(id) : "memory")

__device__ __forceinline__ void ldsm4(uint32_t* r, uint32_t addr){
    asm volatile("ldmatrix.sync.aligned.m8n8.x4.shared.b16 {%0,%1,%2,%3}, [%4];"
        : "=r"(r[0]), "=r"(r[1]), "=r"(r[2]), "=r"(r[3]) : "r"(addr));
}
__device__ __forceinline__ void mma_bf16(float* d, const uint32_t* a, const uint32_t* b){
    asm volatile(
        "mma.sync.aligned.m16n8k16.row.col.f32.bf16.bf16.f32 "
        "{%0,%1,%2,%3}, {%4,%5,%6,%7}, {%8,%9}, {%0,%1,%2,%3};"
        : "+f"(d[0]), "+f"(d[1]), "+f"(d[2]), "+f"(d[3])
        : "r"(a[0]), "r"(a[1]), "r"(a[2]), "r"(a[3]), "r"(b[0]), "r"(b[1]));
}

// ---------------- device scratch ----------------
__device__ __align__(16) float g_Xin[SEQL*BH];
__device__ __align__(16) float g_prev0[BH];
__device__ __align__(16) float g_prev1[BH];
__device__ __align__(16) float g_z0[BH];
__device__ __align__(16) float g_z1[BH];
__device__ __align__(16) float g_part[32*BH];
// bf16 hi/lo activation operands
__device__ __align__(16) __nv_bfloat16 b_prev0_h[BH], b_prev0_l[BH];
__device__ __align__(16) __nv_bfloat16 b_prev1_h[BH], b_prev1_l[BH];
__device__ __align__(16) __nv_bfloat16 b_rp0_h[BH],   b_rp0_l[BH];
__device__ __align__(16) __nv_bfloat16 b_rp1_h[BH],   b_rp1_l[BH];
__device__ __align__(16) __nv_bfloat16 b_r0pre_h[BH], b_r0pre_l[BH];
__device__ __align__(16) __nv_bfloat16 b_f0pre_h[BH], b_f0pre_l[BH];
__device__ __align__(16) __nv_bfloat16 b_h0pre_h[BH], b_h0pre_l[BH];
// recurrence weights: 0=Ur0 1=Uf0 2=Uh0 3=Wr1 4=Ur1 5=Wf1 6=Uf1 7=Wh1 8=Uh1
__device__ __align__(16) __nv_bfloat16 gRW_hi[9*HH], gRW_lo[9*HH];
// k_xin operands
__device__ __align__(16) __nv_bfloat16 gX_hi[SEQL*BH], gX_lo[SEQL*BH];
__device__ __align__(16) __nv_bfloat16 gWin_hi[HH], gWin_lo[HH];
// output GEMM operands
__device__ __align__(16) __nv_bfloat16 gH_hi[SEQL*BH], gH_lo[SEQL*BH];
__device__ __align__(16) __nv_bfloat16 gW_hi[(size_t)VOCAB*HID], gW_lo[(size_t)VOCAB*HID];

// persistent-kernel coordination (monotone -> graph-replay safe)
__device__ unsigned g_barCnt = 0;
__device__ volatile unsigned g_barGen = 0;
__device__ unsigned g_tdone  = 0;    // monotone finished-timestep counter
__device__ unsigned g_jobCtr = 0;    // monotone output-job claim counter

// barrier over `count` CTAs (callers guarantee exactly `count` participants)
__device__ __forceinline__ void ctabar(unsigned count){
    __threadfence();
    BARX(1);
    if (threadIdx.x == 0){
        unsigned g = g_barGen;
        if (atomicAdd(&g_barCnt, 1u) == count - 1u){
            g_barCnt = 0;
            __threadfence();
            g_barGen = g + 1u;
        } else {
            while (g_barGen == g) { __nanosleep(32); }
        }
        __threadfence();
    }
    BARX(1);
}

__device__ __forceinline__ void split_store(__nv_bfloat16* hi, __nv_bfloat16* lo, size_t i, float v){
    __nv_bfloat16 h = __float2bfloat16_rn(v);
    hi[i] = h;
    lo[i] = __float2bfloat16_rn(v - __bfloat162float(h));
}
__device__ __forceinline__ void split_store4(__nv_bfloat16* hi, __nv_bfloat16* lo, size_t i, float4 v){
    __nv_bfloat162 h0 = __floats2bfloat162_rn(v.x, v.y);
    __nv_bfloat162 h1 = __floats2bfloat162_rn(v.z, v.w);
    __nv_bfloat162 l0 = __floats2bfloat162_rn(v.x - __low2float(h0),  v.y - __high2float(h0));
    __nv_bfloat162 l1 = __floats2bfloat162_rn(v.z - __low2float(h1),  v.w - __high2float(h1));
    *(__nv_bfloat162*)(hi + i)     = h0;
    *(__nv_bfloat162*)(hi + i + 2) = h1;
    *(__nv_bfloat162*)(lo + i)     = l0;
    *(__nv_bfloat162*)(lo + i + 2) = l1;
}
#define V4ADD(a,b) do{ (a).x+=(b).x; (a).y+=(b).y; (a).z+=(b).z; (a).w+=(b).w; }while(0)

// ---------------- standalone 128x128 HMMA kernel (Xin only) ----------------
#define OSTAGE 40960
#define OSMEM  (2*OSTAGE)
#define OKIT   (HID/32)

__global__ void __launch_bounds__(256,1) k_mma128(
    const __nv_bfloat16* __restrict__ Ah, const __nv_bfloat16* __restrict__ Al,
    const __nv_bfloat16* __restrict__ Bh, const __nv_bfloat16* __restrict__ Bl,
    float* __restrict__ C, size_t ldc, const float* __restrict__ bias)
{
    extern __shared__ __align__(128) char smem[];
    const uint32_t sb = smem_u32(smem);
    const int tid  = threadIdx.x;
    const int lane = tid & 31;
    const int wid  = tid >> 5;
    const int wm   = wid >> 2;
    const int wn   = wid & 3;
    const int m0 = blockIdx.x * 128;
    const int n0 = blockIdx.y * 128;

    const int rowg = tid >> 2;
    const int seg  = tid & 3;
    const uint32_t soff = (uint32_t)rowg*80 + seg*16;
    const __nv_bfloat16* pAh = Ah + (size_t)(m0 + rowg)*HID + seg*8;
    const __nv_bfloat16* pAl = Al + (size_t)(m0 + rowg)*HID + seg*8;
    const __nv_bfloat16* pBh = Bh + (size_t)(n0 + rowg)*HID + seg*8;
    const __nv_bfloat16* pBl = Bl + (size_t)(n0 + rowg)*HID + seg*8;
    const size_t rstep = (size_t)64*HID;

    auto issue = [&](int buf, int k0){
        uint32_t s0 = sb + buf*OSTAGE;
        CP16(s0 +         soff,         pAh + k0);
        CP16(s0 +         soff + 64*80, pAh + k0 + rstep);
        CP16(s0 + 10240 + soff,         pAl + k0);
        CP16(s0 + 10240 + soff + 64*80, pAl + k0 + rstep);
        CP16(s0 + 20480 + soff,         pBh + k0);
        CP16(s0 + 20480 + soff + 64*80, pBh + k0 + rstep);
        CP16(s0 + 30720 + soff,         pBl + k0);
        CP16(s0 + 30720 + soff + 64*80, pBl + k0 + rstep);
    };

    const int rowA = (lane & 7) + ((lane >> 3) & 1)*8;
    const uint32_t aoff = (uint32_t)(wm*64 + rowA)*80 + (uint32_t)(lane >> 4)*16;
    const int rowB = (lane & 7) + (lane >> 4)*8;
    const uint32_t boff = 20480u + (uint32_t)(wn*32 + rowB)*80 + (uint32_t)((lane >> 3) & 1)*16;

    float acc[4][4][4];
#pragma unroll
    for (int mi = 0; mi < 4; mi++)
#pragma unroll
        for (int ni = 0; ni < 4; ni++)
#pragma unroll
            for (int r = 0; r < 4; r++) acc[mi][ni][r] = 0.f;

    issue(0, 0);
    CP_COMMIT();

    for (int s = 0; s < OKIT; s++){
        if (s + 1 < OKIT){ issue((s+1)&1, (s+1)*32); CP_COMMIT(); CP_WAIT(1); }
        else CP_WAIT(0);
        __syncthreads();

        const uint32_t st = sb + (s&1)*OSTAGE;
#pragma unroll
        for (int kk = 0; kk < 2; kk++){
            uint32_t aH[4][4], aL[4][4], bH[4][2], bL[4][2];
#pragma unroll
            for (int mi = 0; mi < 4; mi++){
                ldsm4(aH[mi], st +         aoff + mi*(16*80) + kk*32);
                ldsm4(aL[mi], st + 10240 + aoff + mi*(16*80) + kk*32);
            }
#pragma unroll
            for (int p = 0; p < 2; p++){
                uint32_t t[4];
                ldsm4(t, st +         boff + p*(16*80) + kk*32);
                bH[2*p][0]=t[0]; bH[2*p][1]=t[1]; bH[2*p+1][0]=t[2]; bH[2*p+1][1]=t[3];
                ldsm4(t, st + 10240 + boff + p*(16*80) + kk*32);
                bL[2*p][0]=t[0]; bL[2*p][1]=t[1]; bL[2*p+1][0]=t[2]; bL[2*p+1][1]=t[3];
            }
#pragma unroll
            for (int mi = 0; mi < 4; mi++)
#pragma unroll
                for (int ni = 0; ni < 4; ni++){
                    mma_bf16(acc[mi][ni], aH[mi], bH[ni]);
                    mma_bf16(acc[mi][ni], aH[mi], bL[ni]);
                    mma_bf16(acc[mi][ni], aL[mi], bH[ni]);
                }
        }
        __syncthreads();
    }

    const int mBase = m0 + wm*64 + (lane >> 2);
    const int nBase = n0 + wn*32 + (lane & 3)*2;
    float2 bv[4];
#pragma unroll
    for (int ni = 0; ni < 4; ni++)
        bv[ni] = bias ? *(const float2*)&bias[nBase + ni*8] : make_float2(0.f, 0.f);
#pragma unroll
    for (int mi = 0; mi < 4; mi++)
#pragma unroll
        for (int ni = 0; ni < 4; ni++)
#pragma unroll
            for (int r = 0; r < 2; r++){
                int m = mBase + mi*16 + r*8;
                float2 v = make_float2(acc[mi][ni][2*r] + bv[ni].x,
                                       acc[mi][ni][2*r+1] + bv[ni].y);
                *(float2*)&C[(size_t)m*ldc + nBase + ni*8] = v;
            }
}

// ---------------- shared 64x128 HMMA core (rec partials OR logits tiles) ----------------
#define RSTAGE   30720
#define RECSMEM  (2*RSTAGE)                 // 61440
#define TOTSMEM  (RECSMEM + 16)             // + claim slot

__device__ __noinline__ void mma_core64(
    const __nv_bfloat16* __restrict__ Ah, const __nv_bfloat16* __restrict__ Al,
    const __nv_bfloat16* __restrict__ Bh, const __nv_bfloat16* __restrict__ Bl,
    int k0, int kLen,
    float* __restrict__ C, unsigned ldc, int m0, int n0,
    const float* __restrict__ bias)
{
    extern __shared__ __align__(128) char smem[];
    const uint32_t sb = smem_u32(smem);
    const int tid  = threadIdx.x;
    const int lane = tid & 31;
    const int wn   = tid >> 5;

    auto issue = [&](int buf, int kofs){
        uint32_t s0 = sb + buf*RSTAGE;
#pragma unroll
        for (int i = 0; i < 2; i++){
            int idx = tid + i*128, row = idx >> 2, sg = idx & 3;
            uint32_t off = (uint32_t)row*80 + sg*16;
            size_t g = (size_t)row*HID + kofs + sg*8;
            CP16(s0 +        off, Ah + g);
            CP16(s0 + 5120 + off, Al + g);
        }
#pragma unroll
        for (int i = 0; i < 4; i++){
            int idx = tid + i*128, row = idx >> 2, sg = idx & 3;
            uint32_t off = (uint32_t)row*80 + sg*16;
            size_t g = (size_t)row*HID + kofs + sg*8;
            CP16(s0 + 10240 + off, Bh + g);
            CP16(s0 + 20480 + off, Bl + g);
        }
    };

    const int rowA = (lane & 7) + ((lane >> 3) & 1)*8;
    const uint32_t aoff = (uint32_t)rowA*80 + (uint32_t)(lane >> 4)*16;
    const int rowB = (lane & 7) + (lane >> 4)*8;
    const uint32_t boff = 10240u + (uint32_t)(wn*32 + rowB)*80 + (uint32_t)((lane >> 3) & 1)*16;

    float acc[4][4][4];
#pragma unroll
    for (int mi = 0; mi < 4; mi++)
#pragma unroll
        for (int ni = 0; ni < 4; ni++)
#pragma unroll
            for (int r = 0; r < 4; r++) acc[mi][ni][r] = 0.f;

    const int nst = kLen >> 5;
    issue(0, k0); CP_COMMIT();

    for (int s = 0; s < nst; s++){
        if (s + 1 < nst){ issue((s+1)&1, k0 + (s+1)*32); CP_COMMIT(); CP_WAIT(1); }
        else CP_WAIT(0);
        BARX(1);

        const uint32_t st = sb + (s&1)*RSTAGE;
#pragma unroll
        for (int kk = 0; kk < 2; kk++){
            uint32_t aH[4][4], aL[4][4], bH[4][2], bL[4][2];
#pragma unroll
            for (int mi = 0; mi < 4; mi++){
                ldsm4(aH[mi], st +        aoff + mi*(16*80) + kk*32);
                ldsm4(aL[mi], st + 5120 + aoff + mi*(16*80) + kk*32);
            }
#pragma unroll
            for (int p = 0; p < 2; p++){
                uint32_t tr[4];
                ldsm4(tr, st +         boff + p*(16*80) + kk*32);
                bH[2*p][0]=tr[0]; bH[2*p][1]=tr[1]; bH[2*p+1][0]=tr[2]; bH[2*p+1][1]=tr[3];
                ldsm4(tr, st + 10240 + boff + p*(16*80) + kk*32);
                bL[2*p][0]=tr[0]; bL[2*p][1]=tr[1]; bL[2*p+1][0]=tr[2]; bL[2*p+1][1]=tr[3];
            }
#pragma unroll
            for (int mi = 0; mi < 4; mi++)
#pragma unroll
                for (int ni = 0; ni < 4; ni++){
                    mma_bf16(acc[mi][ni], aH[mi], bH[ni]);
                    mma_bf16(acc[mi][ni], aH[mi], bL[ni]);
                    mma_bf16(acc[mi][ni], aL[mi], bH[ni]);
                }
        }
        BARX(1);
    }

    const int mBase = m0 + (lane >> 2);
    const int nBase = n0 + wn*32 + (lane & 3)*2;
    float2 bv[4];
#pragma unroll
    for (int ni = 0; ni < 4; ni++)
        bv[ni] = bias ? *(const float2*)&bias[nBase + ni*8] : make_float2(0.f, 0.f);
#pragma unroll
    for (int mi = 0; mi < 4; mi++)
#pragma unroll
        for (int ni = 0; ni < 4; ni++)
#pragma unroll
            for (int r = 0; r < 2; r++){
                int m = mBase + mi*16 + r*8;
                float2 v = make_float2(acc[mi][ni][2*r] + bv[ni].x,
                                       acc[mi][ni][2*r+1] + bv[ni].y);
                *(float2*)&C[(size_t)m*ldc + nBase + ni*8] = v;
            }
}

// recurrence job bodies -----------------------------------------------------
__device__ __forceinline__ void gates0_body(int nt, int gate, int ks){
    size_t wofs = (size_t)gate*HH + (size_t)nt*128*HID;
    mma_core64(b_prev0_h, b_prev0_l, gRW_hi + wofs, gRW_lo + wofs,
               ks*128, 128, g_part + (size_t)(16 + gate*8 + ks)*BH, HID, 0, nt*128, nullptr);
}
__device__ __forceinline__ void last_body(int nt, int ks){
    const __nv_bfloat16 *Ah, *Al; int widx, k0;
    if (ks < 8){ Ah = b_h0pre_h; Al = b_h0pre_l; widx = 7; k0 = ks*128; }
    else       { Ah = b_rp1_h;   Al = b_rp1_l;   widx = 8; k0 = (ks-8)*128; }
    size_t wofs = (size_t)widx*HH + (size_t)nt*128*HID;
    mma_core64(Ah, Al, gRW_hi + wofs, gRW_lo + wofs,
               k0, 128, g_part + (size_t)ks*BH, HID, 0, nt*128, nullptr);
}
__device__ __forceinline__ void mid_job(int j){
    int job = j >> 6;
    int r   = j & 63;
    int nt  = r & 7;
    int ks  = r >> 3;
    const __nv_bfloat16 *Ah, *Al; int widx, k0, kLen;
    if (job == 0){ Ah = b_rp0_h; Al = b_rp0_l; widx = 2; k0 = ks*128; kLen = 128; }
    else {
        int wW = (job == 1) ? 3 : 5;
        int wU = (job == 1) ? 4 : 6;
        if (ks < 4){
            Ah = (job == 1) ? b_r0pre_h : b_f0pre_h;
            Al = (job == 1) ? b_r0pre_l : b_f0pre_l;
            widx = wW; k0 = ks*256;
        } else {
            Ah = b_prev1_h; Al = b_prev1_l;
            widx = wU; k0 = (ks-4)*256;
        }
        kLen = 256;
    }
    size_t wofs = (size_t)widx*HH + (size_t)nt*128*HID;
    mma_core64(Ah, Al, gRW_hi + wofs, gRW_lo + wofs,
               k0, kLen, g_part + (size_t)(job*8 + ks)*BH, HID, 0, nt*128, nullptr);
}

// output worker: claim 64x128 logits tiles, wait for step readiness, compute
__device__ void out_worker(unsigned jobs_base, unsigned tdone_base,
                           const float* __restrict__ outb, float* __restrict__ logits)
{
    extern __shared__ __align__(128) char smem[];
    unsigned* claim = (unsigned*)(smem + RECSMEM);
    const int tid = threadIdx.x;
    for (;;){
        if (tid == 0) *claim = atomicAdd(&g_jobCtr, 1u) - jobs_base;
        BARX(1);
        unsigned j = *claim;
        if (j >= OJOBS) break;
        unsigned tq  = j / OJ_PER_TQ;
        unsigned rem = j - tq*OJ_PER_TQ;
        unsigned nt  = rem >> 3;
        unsigned t   = tq*8u + (rem & 7u);
        if (tid == 0){
            while (*(volatile unsigned*)&g_tdone < tdone_base + t + 1u) __nanosleep(64);
        }
        BARX(1);
        mma_core64(gH_hi + (size_t)t*BH, gH_lo + (size_t)t*BH,
                   gW_hi + (size_t)nt*128*HID, gW_lo + (size_t)nt*128*HID,
                   0, HID, logits, VOCAB, (int)(t*64u), (int)(nt*128u), outb);
    }
}

// fin device functions (1 float4 item per active thread; __ldcg bypasses stale L1)
__device__ __forceinline__ void fin0_one(size_t i, int t,
                                         const float* br0, const float* bf0){
    int n = (int)(i & (HID-1));
    float4 s0 = make_float4(0,0,0,0), s1 = s0;
#pragma unroll
    for (int ks = 0; ks < 8; ks++){
        float4 a = __ldcg((const float4*)&g_part[(size_t)(16+ks)*BH + i]); V4ADD(s0, a);
        float4 b = __ldcg((const float4*)&g_part[(size_t)(24+ks)*BH + i]); V4ADD(s1, b);
    }
    float4 xv = __ldcg((const float4*)&g_Xin[(size_t)t*BH + i]);
    float4 bR = *(const float4*)&br0[n];
    float4 bF = *(const float4*)&bf0[n];
    float4 p0 = __ldcg((const float4*)&g_prev0[i]);
    float4 rp = make_float4(xv.x+bR.x+s0.x, xv.y+bR.y+s0.y, xv.z+bR.z+s0.z, xv.w+bR.w+s0.w);
    float4 fp = make_float4(xv.x+bF.x+s1.x, xv.y+bF.y+s1.y, xv.z+bF.z+s1.z, xv.w+bF.w+s1.w);
    split_store4(b_r0pre_h, b_r0pre_l, i, rp);
    split_store4(b_f0pre_h, b_f0pre_l, i, fp);
    float4 rpv = make_float4(sigmf(rp.x)*p0.x, sigmf(rp.y)*p0.y, sigmf(rp.z)*p0.z, sigmf(rp.w)*p0.w);
    split_store4(b_rp0_h, b_rp0_l, i, rpv);
    *(float4*)&g_z0[i] = make_float4(sigmf(fp.x), sigmf(fp.y), sigmf(fp.z), sigmf(fp.w));
}

__device__ __forceinline__ void fin_mid_one(size_t i, int t, const float* bh0,
                                            const float* br1, const float* bf1){
    int n = (int)(i & (HID-1));
    float4 s0 = make_float4(0,0,0,0), s1 = s0, s2 = s0;
#pragma unroll
    for (int ks = 0; ks < 8; ks++){
        float4 a = __ldcg((const float4*)&g_part[(size_t)ks*BH + i]);      V4ADD(s0, a);
        float4 b = __ldcg((const float4*)&g_part[(size_t)(8+ks)*BH + i]);  V4ADD(s1, b);
        float4 c = __ldcg((const float4*)&g_part[(size_t)(16+ks)*BH + i]); V4ADD(s2, c);
    }
    float4 xv = __ldcg((const float4*)&g_Xin[(size_t)t*BH + i]);
    float4 bH = *(const float4*)&bh0[n];
    float4 ht = make_float4(xv.x+bH.x+s0.x, xv.y+bH.y+s0.y, xv.z+bH.z+s0.z, xv.w+bH.w+s0.w);
    float4 z  = __ldcg((const float4*)&g_z0[i]);
    float4 p0 = __ldcg((const float4*)&g_prev0[i]);
    float4 h0 = make_float4((1.f-z.x)*p0.x + z.x*tanhf(ht.x),
                            (1.f-z.y)*p0.y + z.y*tanhf(ht.y),
                            (1.f-z.z)*p0.z + z.z*tanhf(ht.z),
                            (1.f-z.w)*p0.w + z.w*tanhf(ht.w));
    *(float4*)&g_prev0[i] = h0;
    split_store4(b_prev0_h, b_prev0_l, i, h0);
    split_store4(b_h0pre_h, b_h0pre_l, i, ht);
    float4 bR = *(const float4*)&br1[n];
    float4 bF = *(const float4*)&bf1[n];
    float4 p1 = __ldcg((const float4*)&g_prev1[i]);
    float4 rp1 = make_float4(sigmf(s1.x+bR.x)*p1.x, sigmf(s1.y+bR.y)*p1.y,
                             sigmf(s1.z+bR.z)*p1.z, sigmf(s1.w+bR.w)*p1.w);
    split_store4(b_rp1_h, b_rp1_l, i, rp1);
    *(float4*)&g_z1[i] = make_float4(sigmf(s2.x+bF.x), sigmf(s2.y+bF.y),
                                     sigmf(s2.z+bF.z), sigmf(s2.w+bF.w));
}

__device__ __forceinline__ void finB_one(size_t i, int t, int dogates,
                                         const float* bh1, const float* br0, const float* bf0){
    int n = (int)(i & (HID-1));
    float4 s = make_float4(0,0,0,0);
#pragma unroll
    for (int ks = 0; ks < 16; ks++){
        float4 a = __ldcg((const float4*)&g_part[(size_t)ks*BH + i]); V4ADD(s, a);
    }
    float4 bH = *(const float4*)&bh1[n];
    float4 z  = __ldcg((const float4*)&g_z1[i]);
    float4 p1 = __ldcg((const float4*)&g_prev1[i]);
    float4 h1 = make_float4((1.f-z.x)*p1.x + z.x*tanhf(s.x+bH.x),
                            (1.f-z.y)*p1.y + z.y*tanhf(s.y+bH.y),
                            (1.f-z.z)*p1.z + z.z*tanhf(s.z+bH.z),
                            (1.f-z.w)*p1.w + z.w*tanhf(s.w+bH.w));
    *(float4*)&g_prev1[i] = h1;
    split_store4(b_prev1_h, b_prev1_l, i, h1);
    split_store4(gH_hi, gH_lo, (size_t)t*BH + i, h1);
    if (dogates){
        float4 s0 = make_float4(0,0,0,0), s1 = s0;
#pragma unroll
        for (int ks = 0; ks < 8; ks++){
            float4 a = __ldcg((const float4*)&g_part[(size_t)(16+ks)*BH + i]); V4ADD(s0, a);
            float4 b = __ldcg((const float4*)&g_part[(size_t)(24+ks)*BH + i]); V4ADD(s1, b);
        }
        float4 xv = __ldcg((const float4*)&g_Xin[(size_t)(t+1)*BH + i]);
        float4 bR = *(const float4*)&br0[n];
        float4 bF = *(const float4*)&bf0[n];
        float4 p0 = __ldcg((const float4*)&g_prev0[i]);
        float4 rp = make_float4(xv.x+bR.x+s0.x, xv.y+bR.y+s0.y, xv.z+bR.z+s0.z, xv.w+bR.w+s0.w);
        float4 fp = make_float4(xv.x+bF.x+s1.x, xv.y+bF.y+s1.y, xv.z+bF.z+s1.z, xv.w+bF.w+s1.w);
        split_store4(b_r0pre_h, b_r0pre_l, i, rp);
        split_store4(b_f0pre_h, b_f0pre_l, i, fp);
        float4 rpv = make_float4(sigmf(rp.x)*p0.x, sigmf(rp.y)*p0.y, sigmf(rp.z)*p0.z, sigmf(rp.w)*p0.w);
        split_store4(b_rp0_h, b_rp0_l, i, rpv);
        *(float4*)&g_z0[i] = make_float4(sigmf(fp.x), sigmf(fp.y), sigmf(fp.z), sigmf(fp.w));
    }
}

// ---------------- persistent kernel: 256 rec CTAs + 128 output CTAs ----------------
__global__ void __launch_bounds__(128,3) k_recur(
    const float* __restrict__ br0, const float* __restrict__ bf0,
    const float* __restrict__ bh0, const float* __restrict__ br1,
    const float* __restrict__ bf1, const float* __restrict__ bh1,
    const float* __restrict__ outb, float* __restrict__ logits)
{
    const int b   = blockIdx.x;
    const int tid = threadIdx.x;

    // per-invocation bases (previous invocation fully finished -> stable)
    unsigned tdone_base = *(volatile unsigned*)&g_tdone;
    unsigned jobs_base  = *(volatile unsigned*)&g_jobCtr;

    // entry rendezvous over ALL CTAs: bases read before any claims/publishes
    ctabar(NTOT);

    if (b >= NREC){
        out_worker(jobs_base, tdone_base, outb, logits);
        return;
    }

    // ---- recurrence CTA ----
    const bool finT = (tid < 64);
    const size_t item = ((size_t)b*64 + tid)*4;

    if (b < 128) gates0_body((b>>3)&7, b>>6, b&7);
    ctabar(NREC);
    if (finT) fin0_one(item, 0, br0, bf0);
    ctabar(NREC);

    for (int t = 0; t < SEQL; t++){
        if (b < 192) mid_job(b);
        ctabar(NREC);
        if (finT) fin_mid_one(item, t, bh0, br1, bf1);
        ctabar(NREC);
        if (b < 128) last_body(b >> 4, b & 15);
        else if (t < SEQL-1){
            int r = b - 128;
            gates0_body((r>>3)&7, r>>6, r&7);
        }
        ctabar(NREC);
        if (finT) finB_one(item, t, (t < SEQL-1) ? 1 : 0, bh1, br0, bf0);
        ctabar(NREC);
        if (b == 0 && tid == 0)
            *(volatile unsigned*)&g_tdone = tdone_base + (unsigned)(t + 1);
    }

    // recurrence done: rec CTAs join the output job pool
    out_worker(jobs_base, tdone_base, outb, logits);
}

// ---------------- conversion kernels ----------------
__global__ void k_init(const float* __restrict__ hid){
    int i = blockIdx.x*blockDim.x + threadIdx.x;
    if (i < BH){
        float v = hid[i];
        g_prev0[i] = v; split_store(b_prev0_h, b_prev0_l, i, v);
    } else {
        int j = i - BH;
        float v = hid[i];
        g_prev1[j] = v; split_store(b_prev1_h, b_prev1_l, j, v);
    }
}

__global__ void k_split(const float* __restrict__ src,
                        __nv_bfloat16* __restrict__ hi, __nv_bfloat16* __restrict__ lo){
    size_t i4 = (size_t)blockIdx.x*blockDim.x + threadIdx.x;
    float4 v = *(const float4*)(src + i4*4);
    split_store4(hi, lo, i4*4, v);
}

__global__ void k_cvtRW(const float* __restrict__ Ur, const float* __restrict__ Uf,
                        const float* __restrict__ Uh, const float* __restrict__ Wr1,
                        const float* __restrict__ Wf1, const float* __restrict__ Wh1){
    const float* srcs[9] = {Ur, Uf, Uh, Wr1, Ur + HH, Wf1, Uf + HH, Wh1, Uh + HH};
    int m = blockIdx.y;
    size_t i4 = (size_t)blockIdx.x*blockDim.x + threadIdx.x;
    float4 v = *(const float4*)(srcs[m] + i4*4);
    split_store4(gRW_hi, gRW_lo, (size_t)m*HH + i4*4, v);
}

__global__ void k_cvtX(const int* __restrict__ toks, const float* __restrict__ emb){
    size_t i4 = (size_t)blockIdx.x*blockDim.x + threadIdx.x;
    int row  = (int)(i4 >> 8);
    int colq = (int)(i4 & 255);
    int tok  = toks[row];
    float4 v = *(const float4*)(emb + (size_t)tok*EMBD + colq*4);
    v.x *= SQRTE; v.y *= SQRTE; v.z *= SQRTE; v.w *= SQRTE;
    split_store4(gX_hi, gX_lo, i4*4, v);
}

__global__ void k_copy(float* __restrict__ dst){
    int i = blockIdx.x*blockDim.x + threadIdx.x;
    dst[i] = (i < BH) ? g_prev0[i] : g_prev1[i - BH];
}

// ---------------- launch ----------------
extern "C" void kernel_launch(void* const* d_in, const int* in_sizes, int n_in,
                              void* d_out, int out_size) {
    const int*   toks = (const int*)  d_in[0];
    const float* hid  = (const float*)d_in[1];
    const float* emb  = (const float*)d_in[2];
    const float* Win  = (const float*)d_in[3];
    const float* Wr1  = (const float*)d_in[4];
    const float* Wf1  = (const float*)d_in[5];
    const float* Wh1  = (const float*)d_in[6];
    const float* Ur   = (const float*)d_in[7];
    const float* br   = (const float*)d_in[8];
    const float* Uf   = (const float*)d_in[9];
    const float* bf   = (const float*)d_in[10];
    const float* Uh   = (const float*)d_in[11];
    const float* bh   = (const float*)d_in[12];
    const float* outW = (const float*)d_in[13];
    const float* outb = (const float*)d_in[14];
    float* out = (float*)d_out;

    const float *br0 = br, *br1 = br + HID;
    const float *bf0 = bf, *bf1 = bf + HID;
    const float *bh0 = bh, *bh1 = bh + HID;

    void *pXh, *pXl, *pWinh, *pWinl, *pWh, *pWl, *pXin;
    cudaGetSymbolAddress(&pXh,  gX_hi);    cudaGetSymbolAddress(&pXl,  gX_lo);
    cudaGetSymbolAddress(&pWinh, gWin_hi); cudaGetSymbolAddress(&pWinl, gWin_lo);
    cudaGetSymbolAddress(&pWh,  gW_hi);    cudaGetSymbolAddress(&pWl,  gW_lo);
    cudaGetSymbolAddress(&pXin, g_Xin);

    cudaFuncSetAttribute(k_mma128, cudaFuncAttributeMaxDynamicSharedMemorySize, OSMEM);
    cudaFuncSetAttribute(k_recur,  cudaFuncAttributeMaxDynamicSharedMemorySize, TOTSMEM);

    k_init<<<2*BH/256, 256>>>(hid);
    k_split<<<((size_t)VOCAB*HID/4)/256, 256>>>(outW, (__nv_bfloat16*)pWh, (__nv_bfloat16*)pWl);
    k_split<<<(HH/4)/256, 256>>>(Win, (__nv_bfloat16*)pWinh, (__nv_bfloat16*)pWinl);
    k_cvtRW<<<dim3(HH/4/256, 9), 256>>>(Ur, Uf, Uh, Wr1, Wf1, Wh1);
    k_cvtX<<<(SEQL*BATCH*EMBD/4)/256, 256>>>(toks, emb);
    // Xin = X @ Win^T  (4096 x 1024)
    k_mma128<<<dim3(32,8), 256, OSMEM>>>((__nv_bfloat16*)pXh, (__nv_bfloat16*)pXl,
                                         (__nv_bfloat16*)pWinh, (__nv_bfloat16*)pWinl,
                                         (float*)pXin, HID, nullptr);

    // fused persistent kernel: recurrence (256 CTAs) + overlapped output GEMM (128 CTAs)
    k_recur<<<NTOT, 128, TOTSMEM>>>(br0, bf0, bh0, br1, bf1, bh1, outb, out);

    if ((size_t)out_size >= LOGITS_N + 2*(size_t)BH)
        k_copy<<<2*BH/256, 256>>>(out + LOGITS_N);
}

// round 14
// speedup vs baseline: 1.4652x; 1.1266x over previous
#include <cuda_runtime.h>
#include <cuda_bf16.h>
#include <math.h>
#include <stdint.h>

// ---------------- problem constants ----------------
#define SEQL  64
#define BATCH 64
#define HID   1024
#define EMBD  1024
#define VOCAB 32000
#define BH    (BATCH*HID)            // 65536
#define LOGITS_N ((size_t)SEQL*BATCH*VOCAB)
#define SQRTE 32.0f
#define HH    (HID*HID)
#define NREC  256                    // recurrence CTAs (gridbar group)
#define NTOT  444                    // total persistent CTAs (3/SM x 148 SMs)
#define NOUT  (NTOT - NREC)          // 188 output-GEMM CTAs

// output jobs: 64x128 logits tiles, t-octet ordering for gW L2 reuse
#define OJOBS     16000u             // 64 t * 250 ntiles
#define OJ_PER_TQ 2000u              // 250 * 8

typedef unsigned long long u64;

__device__ __forceinline__ float sigmf(float x){ return 1.0f/(1.0f + expf(-x)); }

// ---------------- smem / async-copy / mma helpers ----------------
__device__ __forceinline__ uint32_t smem_u32(const void* p){
    uint32_t a;
    asm("{ .reg .u64 t; cvta.to.shared.u64 t, %1; cvt.u32.u64 %0, t; }" : "=r"(a) : "l"(p));
    return a;
}
#define CP16(sa, gp) \
    asm volatile("cp.async.cg.shared.global [%0], [%1], 16;" :: "r"((uint32_t)(sa)), "l"(gp) : "memory")
#define CP_COMMIT() asm volatile("cp.async.commit_group;" ::: "memory")
#define CP_WAIT(n)  asm volatile("cp.async.wait_group %0;" :: "n"(n) : "memory")
#define BARX(id)    asm volatile("bar.sync %0, 128;" :: "r"(id) : "memory")

__device__ __forceinline__ void ldsm4(uint32_t* r, uint32_t addr){
    asm volatile("ldmatrix.sync.aligned.m8n8.x4.shared.b16 {%0,%1,%2,%3}, [%4];"
        : "=r"(r[0]), "=r"(r[1]), "=r"(r[2]), "=r"(r[3]) : "r"(addr));
}
__device__ __forceinline__ void mma_bf16(float* d, const uint32_t* a, const uint32_t* b){
    asm volatile(
        "mma.sync.aligned.m16n8k16.row.col.f32.bf16.bf16.f32 "
        "{%0,%1,%2,%3}, {%4,%5,%6,%7}, {%8,%9}, {%0,%1,%2,%3};"
        : "+f"(d[0]), "+f"(d[1]), "+f"(d[2]), "+f"(d[3])
        : "r"(a[0]), "r"(a[1]), "r"(a[2]), "r"(a[3]), "r"(b[0]), "r"(b[1]));
}

// ---------------- device scratch ----------------
__device__ __align__(16) float g_Xin[SEQL*BH];
__device__ __align__(16) float g_prev0[BH];
__device__ __align__(16) float g_prev1[BH];
__device__ __align__(16) float g_z0[BH];
__device__ __align__(16) float g_z1[BH];
__device__ __align__(16) float g_part[32*BH];
// bf16 hi/lo activation operands
__device__ __align__(16) __nv_bfloat16 b_prev0_h[BH], b_prev0_l[BH];
__device__ __align__(16) __nv_bfloat16 b_prev1_h[BH], b_prev1_l[BH];
__device__ __align__(16) __nv_bfloat16 b_rp0_h[BH],   b_rp0_l[BH];
__device__ __align__(16) __nv_bfloat16 b_rp1_h[BH],   b_rp1_l[BH];
__device__ __align__(16) __nv_bfloat16 b_r0pre_h[BH], b_r0pre_l[BH];
__device__ __align__(16) __nv_bfloat16 b_f0pre_h[BH], b_f0pre_l[BH];
__device__ __align__(16) __nv_bfloat16 b_h0pre_h[BH], b_h0pre_l[BH];
// recurrence weights: 0=Ur0 1=Uf0 2=Uh0 3=Wr1 4=Ur1 5=Wf1 6=Uf1 7=Wh1 8=Uh1
__device__ __align__(16) __nv_bfloat16 gRW_hi[9*HH], gRW_lo[9*HH];
// k_xin operands
__device__ __align__(16) __nv_bfloat16 gX_hi[SEQL*BH], gX_lo[SEQL*BH];
__device__ __align__(16) __nv_bfloat16 gWin_hi[HH], gWin_lo[HH];
// output GEMM operands
__device__ __align__(16) __nv_bfloat16 gH_hi[SEQL*BH], gH_lo[SEQL*BH];
__device__ __align__(16) __nv_bfloat16 gW_hi[(size_t)VOCAB*HID], gW_lo[(size_t)VOCAB*HID];

// persistent-kernel coordination (monotone -> graph-replay safe)
__device__ unsigned g_barCnt = 0;
__device__ volatile unsigned g_barGen = 0;
__device__ unsigned g_barCnt2 = 0;           // out-group barrier (disjoint counters)
__device__ volatile unsigned g_barGen2 = 0;
__device__ unsigned g_tdone  = 0;            // monotone finished-timestep counter
__device__ unsigned g_jobCtr = 0;            // monotone output-job claim counter

// barrier over `count` CTAs of the rec/entry group (counter set 1)
__device__ __forceinline__ void ctabar(unsigned count){
    __threadfence();
    BARX(1);
    if (threadIdx.x == 0){
        unsigned g = g_barGen;
        if (atomicAdd(&g_barCnt, 1u) == count - 1u){
            g_barCnt = 0;
            __threadfence();
            g_barGen = g + 1u;
        } else {
            while (g_barGen == g) { __nanosleep(32); }
        }
        __threadfence();
    }
    BARX(1);
}
// barrier over the NOUT out-group CTAs (counter set 2)
__device__ __forceinline__ void outbar(){
    __threadfence();
    BARX(1);
    if (threadIdx.x == 0){
        unsigned g = g_barGen2;
        if (atomicAdd(&g_barCnt2, 1u) == (unsigned)NOUT - 1u){
            g_barCnt2 = 0;
            __threadfence();
            g_barGen2 = g + 1u;
        } else {
            while (g_barGen2 == g) { __nanosleep(32); }
        }
        __threadfence();
    }
    BARX(1);
}

__device__ __forceinline__ void split_store(__nv_bfloat16* hi, __nv_bfloat16* lo, size_t i, float v){
    __nv_bfloat16 h = __float2bfloat16_rn(v);
    hi[i] = h;
    lo[i] = __float2bfloat16_rn(v - __bfloat162float(h));
}
__device__ __forceinline__ void split_store4(__nv_bfloat16* hi, __nv_bfloat16* lo, size_t i, float4 v){
    __nv_bfloat162 h0 = __floats2bfloat162_rn(v.x, v.y);
    __nv_bfloat162 h1 = __floats2bfloat162_rn(v.z, v.w);
    __nv_bfloat162 l0 = __floats2bfloat162_rn(v.x - __low2float(h0),  v.y - __high2float(h0));
    __nv_bfloat162 l1 = __floats2bfloat162_rn(v.z - __low2float(h1),  v.w - __high2float(h1));
    *(__nv_bfloat162*)(hi + i)     = h0;
    *(__nv_bfloat162*)(hi + i + 2) = h1;
    *(__nv_bfloat162*)(lo + i)     = l0;
    *(__nv_bfloat162*)(lo + i + 2) = l1;
}
#define V4ADD(a,b) do{ (a).x+=(b).x; (a).y+=(b).y; (a).z+=(b).z; (a).w+=(b).w; }while(0)

// ---------------- standalone 128x128 HMMA kernel (Xin only) ----------------
#define OSTAGE 40960
#define OSMEM  (2*OSTAGE)
#define OKIT   (HID/32)

__global__ void __launch_bounds__(256,1) k_mma128(
    const __nv_bfloat16* __restrict__ Ah, const __nv_bfloat16* __restrict__ Al,
    const __nv_bfloat16* __restrict__ Bh, const __nv_bfloat16* __restrict__ Bl,
    float* __restrict__ C, size_t ldc, const float* __restrict__ bias)
{
    extern __shared__ __align__(128) char smem[];
    const uint32_t sb = smem_u32(smem);
    const int tid  = threadIdx.x;
    const int lane = tid & 31;
    const int wid  = tid >> 5;
    const int wm   = wid >> 2;
    const int wn   = wid & 3;
    const int m0 = blockIdx.x * 128;
    const int n0 = blockIdx.y * 128;

    const int rowg = tid >> 2;
    const int seg  = tid & 3;
    const uint32_t soff = (uint32_t)rowg*80 + seg*16;
    const __nv_bfloat16* pAh = Ah + (size_t)(m0 + rowg)*HID + seg*8;
    const __nv_bfloat16* pAl = Al + (size_t)(m0 + rowg)*HID + seg*8;
    const __nv_bfloat16* pBh = Bh + (size_t)(n0 + rowg)*HID + seg*8;
    const __nv_bfloat16* pBl = Bl + (size_t)(n0 + rowg)*HID + seg*8;
    const size_t rstep = (size_t)64*HID;

    auto issue = [&](int buf, int k0){
        uint32_t s0 = sb + buf*OSTAGE;
        CP16(s0 +         soff,         pAh + k0);
        CP16(s0 +         soff + 64*80, pAh + k0 + rstep);
        CP16(s0 + 10240 + soff,         pAl + k0);
        CP16(s0 + 10240 + soff + 64*80, pAl + k0 + rstep);
        CP16(s0 + 20480 + soff,         pBh + k0);
        CP16(s0 + 20480 + soff + 64*80, pBh + k0 + rstep);
        CP16(s0 + 30720 + soff,         pBl + k0);
        CP16(s0 + 30720 + soff + 64*80, pBl + k0 + rstep);
    };

    const int rowA = (lane & 7) + ((lane >> 3) & 1)*8;
    const uint32_t aoff = (uint32_t)(wm*64 + rowA)*80 + (uint32_t)(lane >> 4)*16;
    const int rowB = (lane & 7) + (lane >> 4)*8;
    const uint32_t boff = 20480u + (uint32_t)(wn*32 + rowB)*80 + (uint32_t)((lane >> 3) & 1)*16;

    float acc[4][4][4];
#pragma unroll
    for (int mi = 0; mi < 4; mi++)
#pragma unroll
        for (int ni = 0; ni < 4; ni++)
#pragma unroll
            for (int r = 0; r < 4; r++) acc[mi][ni][r] = 0.f;

    issue(0, 0);
    CP_COMMIT();

    for (int s = 0; s < OKIT; s++){
        if (s + 1 < OKIT){ issue((s+1)&1, (s+1)*32); CP_COMMIT(); CP_WAIT(1); }
        else CP_WAIT(0);
        __syncthreads();

        const uint32_t st = sb + (s&1)*OSTAGE;
#pragma unroll
        for (int kk = 0; kk < 2; kk++){
            uint32_t aH[4][4], aL[4][4], bH[4][2], bL[4][2];
#pragma unroll
            for (int mi = 0; mi < 4; mi++){
                ldsm4(aH[mi], st +         aoff + mi*(16*80) + kk*32);
                ldsm4(aL[mi], st + 10240 + aoff + mi*(16*80) + kk*32);
            }
#pragma unroll
            for (int p = 0; p < 2; p++){
                uint32_t t[4];
                ldsm4(t, st +         boff + p*(16*80) + kk*32);
                bH[2*p][0]=t[0]; bH[2*p][1]=t[1]; bH[2*p+1][0]=t[2]; bH[2*p+1][1]=t[3];
                ldsm4(t, st + 10240 + boff + p*(16*80) + kk*32);
                bL[2*p][0]=t[0]; bL[2*p][1]=t[1]; bL[2*p+1][0]=t[2]; bL[2*p+1][1]=t[3];
            }
#pragma unroll
            for (int mi = 0; mi < 4; mi++)
#pragma unroll
                for (int ni = 0; ni < 4; ni++){
                    mma_bf16(acc[mi][ni], aH[mi], bH[ni]);
                    mma_bf16(acc[mi][ni], aH[mi], bL[ni]);
                    mma_bf16(acc[mi][ni], aL[mi], bH[ni]);
                }
        }
        __syncthreads();
    }

    const int mBase = m0 + wm*64 + (lane >> 2);
    const int nBase = n0 + wn*32 + (lane & 3)*2;
    float2 bv[4];
#pragma unroll
    for (int ni = 0; ni < 4; ni++)
        bv[ni] = bias ? *(const float2*)&bias[nBase + ni*8] : make_float2(0.f, 0.f);
#pragma unroll
    for (int mi = 0; mi < 4; mi++)
#pragma unroll
        for (int ni = 0; ni < 4; ni++)
#pragma unroll
            for (int r = 0; r < 2; r++){
                int m = mBase + mi*16 + r*8;
                float2 v = make_float2(acc[mi][ni][2*r] + bv[ni].x,
                                       acc[mi][ni][2*r+1] + bv[ni].y);
                *(float2*)&C[(size_t)m*ldc + nBase + ni*8] = v;
            }
}

// ---------------- shared 64x128 HMMA core (rec partials OR logits tiles) ----------------
#define RSTAGE   30720
#define RECSMEM  (2*RSTAGE)                 // 61440
#define TOTSMEM  (RECSMEM + 16)             // + claim slot

__device__ __noinline__ void mma_core64(
    const __nv_bfloat16* __restrict__ Ah, const __nv_bfloat16* __restrict__ Al,
    const __nv_bfloat16* __restrict__ Bh, const __nv_bfloat16* __restrict__ Bl,
    int k0, int kLen,
    float* __restrict__ C, unsigned ldc, int m0, int n0,
    const float* __restrict__ bias)
{
    extern __shared__ __align__(128) char smem[];
    const uint32_t sb = smem_u32(smem);
    const int tid  = threadIdx.x;
    const int lane = tid & 31;
    const int wn   = tid >> 5;

    auto issue = [&](int buf, int kofs){
        uint32_t s0 = sb + buf*RSTAGE;
#pragma unroll
        for (int i = 0; i < 2; i++){
            int idx = tid + i*128, row = idx >> 2, sg = idx & 3;
            uint32_t off = (uint32_t)row*80 + sg*16;
            size_t g = (size_t)row*HID + kofs + sg*8;
            CP16(s0 +        off, Ah + g);
            CP16(s0 + 5120 + off, Al + g);
        }
#pragma unroll
        for (int i = 0; i < 4; i++){
            int idx = tid + i*128, row = idx >> 2, sg = idx & 3;
            uint32_t off = (uint32_t)row*80 + sg*16;
            size_t g = (size_t)row*HID + kofs + sg*8;
            CP16(s0 + 10240 + off, Bh + g);
            CP16(s0 + 20480 + off, Bl + g);
        }
    };

    const int rowA = (lane & 7) + ((lane >> 3) & 1)*8;
    const uint32_t aoff = (uint32_t)rowA*80 + (uint32_t)(lane >> 4)*16;
    const int rowB = (lane & 7) + (lane >> 4)*8;
    const uint32_t boff = 10240u + (uint32_t)(wn*32 + rowB)*80 + (uint32_t)((lane >> 3) & 1)*16;

    float acc[4][4][4];
#pragma unroll
    for (int mi = 0; mi < 4; mi++)
#pragma unroll
        for (int ni = 0; ni < 4; ni++)
#pragma unroll
            for (int r = 0; r < 4; r++) acc[mi][ni][r] = 0.f;

    const int nst = kLen >> 5;
    issue(0, k0); CP_COMMIT();

    for (int s = 0; s < nst; s++){
        if (s + 1 < nst){ issue((s+1)&1, k0 + (s+1)*32); CP_COMMIT(); CP_WAIT(1); }
        else CP_WAIT(0);
        BARX(1);

        const uint32_t st = sb + (s&1)*RSTAGE;
#pragma unroll
        for (int kk = 0; kk < 2; kk++){
            uint32_t aH[4][4], aL[4][4], bH[4][2], bL[4][2];
#pragma unroll
            for (int mi = 0; mi < 4; mi++){
                ldsm4(aH[mi], st +        aoff + mi*(16*80) + kk*32);
                ldsm4(aL[mi], st + 5120 + aoff + mi*(16*80) + kk*32);
            }
#pragma unroll
            for (int p = 0; p < 2; p++){
                uint32_t tr[4];
                ldsm4(tr, st +         boff + p*(16*80) + kk*32);
                bH[2*p][0]=tr[0]; bH[2*p][1]=tr[1]; bH[2*p+1][0]=tr[2]; bH[2*p+1][1]=tr[3];
                ldsm4(tr, st + 10240 + boff + p*(16*80) + kk*32);
                bL[2*p][0]=tr[0]; bL[2*p][1]=tr[1]; bL[2*p+1][0]=tr[2]; bL[2*p+1][1]=tr[3];
            }
#pragma unroll
            for (int mi = 0; mi < 4; mi++)
#pragma unroll
                for (int ni = 0; ni < 4; ni++){
                    mma_bf16(acc[mi][ni], aH[mi], bH[ni]);
                    mma_bf16(acc[mi][ni], aH[mi], bL[ni]);
                    mma_bf16(acc[mi][ni], aL[mi], bH[ni]);
                }
        }
        BARX(1);
    }

    const int mBase = m0 + (lane >> 2);
    const int nBase = n0 + wn*32 + (lane & 3)*2;
    float2 bv[4];
#pragma unroll
    for (int ni = 0; ni < 4; ni++)
        bv[ni] = bias ? *(const float2*)&bias[nBase + ni*8] : make_float2(0.f, 0.f);
#pragma unroll
    for (int mi = 0; mi < 4; mi++)
#pragma unroll
        for (int ni = 0; ni < 4; ni++)
#pragma unroll
            for (int r = 0; r < 2; r++){
                int m = mBase + mi*16 + r*8;
                float2 v = make_float2(acc[mi][ni][2*r] + bv[ni].x,
                                       acc[mi][ni][2*r+1] + bv[ni].y);
                *(float2*)&C[(size_t)m*ldc + nBase + ni*8] = v;
            }
}

// recurrence job bodies -----------------------------------------------------
__device__ __forceinline__ void gates0_body(int nt, int gate, int ks){
    size_t wofs = (size_t)gate*HH + (size_t)nt*128*HID;
    mma_core64(b_prev0_h, b_prev0_l, gRW_hi + wofs, gRW_lo + wofs,
               ks*128, 128, g_part + (size_t)(16 + gate*8 + ks)*BH, HID, 0, nt*128, nullptr);
}
__device__ __forceinline__ void last_body(int nt, int ks){
    const __nv_bfloat16 *Ah, *Al; int widx, k0;
    if (ks < 8){ Ah = b_h0pre_h; Al = b_h0pre_l; widx = 7; k0 = ks*128; }
    else       { Ah = b_rp1_h;   Al = b_rp1_l;   widx = 8; k0 = (ks-8)*128; }
    size_t wofs = (size_t)widx*HH + (size_t)nt*128*HID;
    mma_core64(Ah, Al, gRW_hi + wofs, gRW_lo + wofs,
               k0, 128, g_part + (size_t)ks*BH, HID, 0, nt*128, nullptr);
}
__device__ __forceinline__ void mid_job(int j){
    int job = j >> 6;
    int r   = j & 63;
    int nt  = r & 7;
    int ks  = r >> 3;
    const __nv_bfloat16 *Ah, *Al; int widx, k0, kLen;
    if (job == 0){ Ah = b_rp0_h; Al = b_rp0_l; widx = 2; k0 = ks*128; kLen = 128; }
    else {
        int wW = (job == 1) ? 3 : 5;
        int wU = (job == 1) ? 4 : 6;
        if (ks < 4){
            Ah = (job == 1) ? b_r0pre_h : b_f0pre_h;
            Al = (job == 1) ? b_r0pre_l : b_f0pre_l;
            widx = wW; k0 = ks*256;
        } else {
            Ah = b_prev1_h; Al = b_prev1_l;
            widx = wU; k0 = (ks-4)*256;
        }
        kLen = 256;
    }
    size_t wofs = (size_t)widx*HH + (size_t)nt*128*HID;
    mma_core64(Ah, Al, gRW_hi + wofs, gRW_lo + wofs,
               k0, kLen, g_part + (size_t)(job*8 + ks)*BH, HID, 0, nt*128, nullptr);
}

// output worker: claim 64x128 logits tiles, wait for step readiness, compute
__device__ void out_worker(unsigned jobs_base, unsigned tdone_base,
                           const float* __restrict__ outb, float* __restrict__ logits)
{
    extern __shared__ __align__(128) char smem[];
    unsigned* claim = (unsigned*)(smem + RECSMEM);
    const int tid = threadIdx.x;
    for (;;){
        if (tid == 0) *claim = atomicAdd(&g_jobCtr, 1u) - jobs_base;
        BARX(1);
        unsigned j = *claim;
        if (j >= OJOBS) break;
        unsigned tq  = j / OJ_PER_TQ;
        unsigned rem = j - tq*OJ_PER_TQ;
        unsigned nt  = rem >> 3;
        unsigned t   = tq*8u + (rem & 7u);
        if (tid == 0){
            while (*(volatile unsigned*)&g_tdone < tdone_base + t + 1u) __nanosleep(64);
        }
        BARX(1);
        mma_core64(gH_hi + (size_t)t*BH, gH_lo + (size_t)t*BH,
                   gW_hi + (size_t)nt*128*HID, gW_lo + (size_t)nt*128*HID,
                   0, HID, logits, VOCAB, (int)(t*64u), (int)(nt*128u), outb);
    }
}

// fin device functions (1 float4 item per active thread; __ldcg bypasses stale L1)
__device__ __forceinline__ void fin0_one(size_t i, int t,
                                         const float* br0, const float* bf0){
    int n = (int)(i & (HID-1));
    float4 s0 = make_float4(0,0,0,0), s1 = s0;
#pragma unroll
    for (int ks = 0; ks < 8; ks++){
        float4 a = __ldcg((const float4*)&g_part[(size_t)(16+ks)*BH + i]); V4ADD(s0, a);
        float4 b = __ldcg((const float4*)&g_part[(size_t)(24+ks)*BH + i]); V4ADD(s1, b);
    }
    float4 xv = __ldcg((const float4*)&g_Xin[(size_t)t*BH + i]);
    float4 bR = *(const float4*)&br0[n];
    float4 bF = *(const float4*)&bf0[n];
    float4 p0 = __ldcg((const float4*)&g_prev0[i]);
    float4 rp = make_float4(xv.x+bR.x+s0.x, xv.y+bR.y+s0.y, xv.z+bR.z+s0.z, xv.w+bR.w+s0.w);
    float4 fp = make_float4(xv.x+bF.x+s1.x, xv.y+bF.y+s1.y, xv.z+bF.z+s1.z, xv.w+bF.w+s1.w);
    split_store4(b_r0pre_h, b_r0pre_l, i, rp);
    split_store4(b_f0pre_h, b_f0pre_l, i, fp);
    float4 rpv = make_float4(sigmf(rp.x)*p0.x, sigmf(rp.y)*p0.y, sigmf(rp.z)*p0.z, sigmf(rp.w)*p0.w);
    split_store4(b_rp0_h, b_rp0_l, i, rpv);
    *(float4*)&g_z0[i] = make_float4(sigmf(fp.x), sigmf(fp.y), sigmf(fp.z), sigmf(fp.w));
}

__device__ __forceinline__ void fin_mid_one(size_t i, int t, const float* bh0,
                                            const float* br1, const float* bf1){
    int n = (int)(i & (HID-1));
    float4 s0 = make_float4(0,0,0,0), s1 = s0, s2 = s0;
#pragma unroll
    for (int ks = 0; ks < 8; ks++){
        float4 a = __ldcg((const float4*)&g_part[(size_t)ks*BH + i]);      V4ADD(s0, a);
        float4 b = __ldcg((const float4*)&g_part[(size_t)(8+ks)*BH + i]);  V4ADD(s1, b);
        float4 c = __ldcg((const float4*)&g_part[(size_t)(16+ks)*BH + i]); V4ADD(s2, c);
    }
    float4 xv = __ldcg((const float4*)&g_Xin[(size_t)t*BH + i]);
    float4 bH = *(const float4*)&bh0[n];
    float4 ht = make_float4(xv.x+bH.x+s0.x, xv.y+bH.y+s0.y, xv.z+bH.z+s0.z, xv.w+bH.w+s0.w);
    float4 z  = __ldcg((const float4*)&g_z0[i]);
    float4 p0 = __ldcg((const float4*)&g_prev0[i]);
    float4 h0 = make_float4((1.f-z.x)*p0.x + z.x*tanhf(ht.x),
                            (1.f-z.y)*p0.y + z.y*tanhf(ht.y),
                            (1.f-z.z)*p0.z + z.z*tanhf(ht.z),
                            (1.f-z.w)*p0.w + z.w*tanhf(ht.w));
    *(float4*)&g_prev0[i] = h0;
    split_store4(b_prev0_h, b_prev0_l, i, h0);
    split_store4(b_h0pre_h, b_h0pre_l, i, ht);
    float4 bR = *(const float4*)&br1[n];
    float4 bF = *(const float4*)&bf1[n];
    float4 p1 = __ldcg((const float4*)&g_prev1[i]);
    float4 rp1 = make_float4(sigmf(s1.x+bR.x)*p1.x, sigmf(s1.y+bR.y)*p1.y,
                             sigmf(s1.z+bR.z)*p1.z, sigmf(s1.w+bR.w)*p1.w);
    split_store4(b_rp1_h, b_rp1_l, i, rp1);
    *(float4*)&g_z1[i] = make_float4(sigmf(s2.x+bF.x), sigmf(s2.y+bF.y),
                                     sigmf(s2.z+bF.z), sigmf(s2.w+bF.w));
}

__device__ __forceinline__ void finB_one(size_t i, int t, int dogates,
                                         const float* bh1, const float* br0, const float* bf0){
    int n = (int)(i & (HID-1));
    float4 s = make_float4(0,0,0,0);
#pragma unroll
    for (int ks = 0; ks < 16; ks++){
        float4 a = __ldcg((const float4*)&g_part[(size_t)ks*BH + i]); V4ADD(s, a);
    }
    float4 bH = *(const float4*)&bh1[n];
    float4 z  = __ldcg((const float4*)&g_z1[i]);
    float4 p1 = __ldcg((const float4*)&g_prev1[i]);
    float4 h1 = make_float4((1.f-z.x)*p1.x + z.x*tanhf(s.x+bH.x),
                            (1.f-z.y)*p1.y + z.y*tanhf(s.y+bH.y),
                            (1.f-z.z)*p1.z + z.z*tanhf(s.z+bH.z),
                            (1.f-z.w)*p1.w + z.w*tanhf(s.w+bH.w));
    *(float4*)&g_prev1[i] = h1;
    split_store4(b_prev1_h, b_prev1_l, i, h1);
    split_store4(gH_hi, gH_lo, (size_t)t*BH + i, h1);
    if (dogates){
        float4 s0 = make_float4(0,0,0,0), s1 = s0;
#pragma unroll
        for (int ks = 0; ks < 8; ks++){
            float4 a = __ldcg((const float4*)&g_part[(size_t)(16+ks)*BH + i]); V4ADD(s0, a);
            float4 b = __ldcg((const float4*)&g_part[(size_t)(24+ks)*BH + i]); V4ADD(s1, b);
        }
        float4 xv = __ldcg((const float4*)&g_Xin[(size_t)(t+1)*BH + i]);
        float4 bR = *(const float4*)&br0[n];
        float4 bF = *(const float4*)&bf0[n];
        float4 p0 = __ldcg((const float4*)&g_prev0[i]);
        float4 rp = make_float4(xv.x+bR.x+s0.x, xv.y+bR.y+s0.y, xv.z+bR.z+s0.z, xv.w+bR.w+s0.w);
        float4 fp = make_float4(xv.x+bF.x+s1.x, xv.y+bF.y+s1.y, xv.z+bF.z+s1.z, xv.w+bF.w+s1.w);
        split_store4(b_r0pre_h, b_r0pre_l, i, rp);
        split_store4(b_f0pre_h, b_f0pre_l, i, fp);
        float4 rpv = make_float4(sigmf(rp.x)*p0.x, sigmf(rp.y)*p0.y, sigmf(rp.z)*p0.z, sigmf(rp.w)*p0.w);
        split_store4(b_rp0_h, b_rp0_l, i, rpv);
        *(float4*)&g_z0[i] = make_float4(sigmf(fp.x), sigmf(fp.y), sigmf(fp.z), sigmf(fp.w));
    }
}

// ---------------- persistent kernel: 256 rec CTAs + 188 output CTAs ----------------
__global__ void __launch_bounds__(128,3) k_recur(
    const float* __restrict__ br0, const float* __restrict__ bf0,
    const float* __restrict__ bh0, const float* __restrict__ br1,
    const float* __restrict__ bf1, const float* __restrict__ bh1,
    const float* __restrict__ outW,
    const float* __restrict__ outb, float* __restrict__ logits)
{
    const int b   = blockIdx.x;
    const int tid = threadIdx.x;

    // per-invocation bases (previous invocation fully finished -> stable)
    unsigned tdone_base = *(volatile unsigned*)&g_tdone;
    unsigned jobs_base  = *(volatile unsigned*)&g_jobCtr;

    // entry rendezvous over ALL CTAs: bases read before any claims/publishes
    ctabar(NTOT);

    if (b >= NREC){
        // ---- out-group prologue: split outW fp32 -> bf16 hi/lo (overlaps rec) ----
        const size_t total4 = (size_t)VOCAB*HID/4;
        for (size_t i4 = (size_t)(b - NREC)*128 + tid; i4 < total4; i4 += (size_t)NOUT*128){
            float4 v = *(const float4*)(outW + i4*4);
            split_store4(gW_hi, gW_lo, i4*4, v);
        }
        outbar();   // gW fully split before any out job reads it
        out_worker(jobs_base, tdone_base, outb, logits);
        return;
    }

    // ---- recurrence CTA ----
    const bool finT = (tid < 64);
    const size_t item = ((size_t)b*64 + tid)*4;

    if (b < 128) gates0_body((b>>3)&7, b>>6, b&7);
    ctabar(NREC);
    if (finT) fin0_one(item, 0, br0, bf0);
    ctabar(NREC);

    for (int t = 0; t < SEQL; t++){
        if (b < 192) mid_job(b);
        ctabar(NREC);
        if (finT) fin_mid_one(item, t, bh0, br1, bf1);
        ctabar(NREC);
        if (b < 128) last_body(b >> 4, b & 15);
        else if (t < SEQL-1){
            int r = b - 128;
            gates0_body((r>>3)&7, r>>6, r&7);
        }
        ctabar(NREC);
        if (finT) finB_one(item, t, (t < SEQL-1) ? 1 : 0, bh1, br0, bf0);
        ctabar(NREC);
        if (b == 0 && tid == 0)
            *(volatile unsigned*)&g_tdone = tdone_base + (unsigned)(t + 1);
    }

    // recurrence done: rec CTAs join the output job pool
    out_worker(jobs_base, tdone_base, outb, logits);
}

// ---------------- conversion kernels ----------------
__global__ void k_init(const float* __restrict__ hid){
    int i = blockIdx.x*blockDim.x + threadIdx.x;
    if (i < BH){
        float v = hid[i];
        g_prev0[i] = v; split_store(b_prev0_h, b_prev0_l, i, v);
    } else {
        int j = i - BH;
        float v = hid[i];
        g_prev1[j] = v; split_store(b_prev1_h, b_prev1_l, j, v);
    }
}

__global__ void k_split(const float* __restrict__ src,
                        __nv_bfloat16* __restrict__ hi, __nv_bfloat16* __restrict__ lo){
    size_t i4 = (size_t)blockIdx.x*blockDim.x + threadIdx.x;
    float4 v = *(const float4*)(src + i4*4);
    split_store4(hi, lo, i4*4, v);
}

__global__ void k_cvtRW(const float* __restrict__ Ur, const float* __restrict__ Uf,
                        const float* __restrict__ Uh, const float* __restrict__ Wr1,
                        const float* __restrict__ Wf1, const float* __restrict__ Wh1){
    const float* srcs[9] = {Ur, Uf, Uh, Wr1, Ur + HH, Wf1, Uf + HH, Wh1, Uh + HH};
    int m = blockIdx.y;
    size_t i4 = (size_t)blockIdx.x*blockDim.x + threadIdx.x;
    float4 v = *(const float4*)(srcs[m] + i4*4);
    split_store4(gRW_hi, gRW_lo, (size_t)m*HH + i4*4, v);
}

__global__ void k_cvtX(const int* __restrict__ toks, const float* __restrict__ emb){
    size_t i4 = (size_t)blockIdx.x*blockDim.x + threadIdx.x;
    int row  = (int)(i4 >> 8);
    int colq = (int)(i4 & 255);
    int tok  = toks[row];
    float4 v = *(const float4*)(emb + (size_t)tok*EMBD + colq*4);
    v.x *= SQRTE; v.y *= SQRTE; v.z *= SQRTE; v.w *= SQRTE;
    split_store4(gX_hi, gX_lo, i4*4, v);
}

__global__ void k_copy(float* __restrict__ dst){
    int i = blockIdx.x*blockDim.x + threadIdx.x;
    dst[i] = (i < BH) ? g_prev0[i] : g_prev1[i - BH];
}

// ---------------- launch ----------------
extern "C" void kernel_launch(void* const* d_in, const int* in_sizes, int n_in,
                              void* d_out, int out_size) {
    const int*   toks = (const int*)  d_in[0];
    const float* hid  = (const float*)d_in[1];
    const float* emb  = (const float*)d_in[2];
    const float* Win  = (const float*)d_in[3];
    const float* Wr1  = (const float*)d_in[4];
    const float* Wf1  = (const float*)d_in[5];
    const float* Wh1  = (const float*)d_in[6];
    const float* Ur   = (const float*)d_in[7];
    const float* br   = (const float*)d_in[8];
    const float* Uf   = (const float*)d_in[9];
    const float* bf   = (const float*)d_in[10];
    const float* Uh   = (const float*)d_in[11];
    const float* bh   = (const float*)d_in[12];
    const float* outW = (const float*)d_in[13];
    const float* outb = (const float*)d_in[14];
    float* out = (float*)d_out;

    const float *br0 = br, *br1 = br + HID;
    const float *bf0 = bf, *bf1 = bf + HID;
    const float *bh0 = bh, *bh1 = bh + HID;

    void *pXh, *pXl, *pWinh, *pWinl, *pXin;
    cudaGetSymbolAddress(&pXh,  gX_hi);    cudaGetSymbolAddress(&pXl,  gX_lo);
    cudaGetSymbolAddress(&pWinh, gWin_hi); cudaGetSymbolAddress(&pWinl, gWin_lo);
    cudaGetSymbolAddress(&pXin, g_Xin);

    cudaFuncSetAttribute(k_mma128, cudaFuncAttributeMaxDynamicSharedMemorySize, OSMEM);
    cudaFuncSetAttribute(k_recur,  cudaFuncAttributeMaxDynamicSharedMemorySize, TOTSMEM);

    k_init<<<2*BH/256, 256>>>(hid);
    k_split<<<(HH/4)/256, 256>>>(Win, (__nv_bfloat16*)pWinh, (__nv_bfloat16*)pWinl);
    k_cvtRW<<<dim3(HH/4/256, 9), 256>>>(Ur, Uf, Uh, Wr1, Wf1, Wh1);
    k_cvtX<<<(SEQL*BATCH*EMBD/4)/256, 256>>>(toks, emb);
    // Xin = X @ Win^T  (4096 x 1024)
    k_mma128<<<dim3(32,8), 256, OSMEM>>>((__nv_bfloat16*)pXh, (__nv_bfloat16*)pXl,
                                         (__nv_bfloat16*)pWinh, (__nv_bfloat16*)pWinl,
                                         (float*)pXin, HID, nullptr);

    // fused persistent kernel: recurrence (256 CTAs) + W-split + output GEMM (188 CTAs)
    k_recur<<<NTOT, 128, TOTSMEM>>>(br0, bf0, bh0, br1, bf1, bh1, outW, outb, out);

    if ((size_t)out_size >= LOGITS_N + 2*(size_t)BH)
        k_copy<<<2*BH/256, 256>>>(out + LOGITS_N);
}

// round 15
// speedup vs baseline: 1.4711x; 1.0040x over previous
#include <cuda_runtime.h>
#include <cuda_bf16.h>
#include <math.h>
#include <stdint.h>

// ---------------- problem constants ----------------
#define SEQL  64
#define BATCH 64
#define HID   1024
#define EMBD  1024
#define VOCAB 32000
#define BH    (BATCH*HID)            // 65536
#define LOGITS_N ((size_t)SEQL*BATCH*VOCAB)
#define SQRTE 32.0f
#define HH    (HID*HID)
#define NREC  256                    // recurrence CTAs
#define NTOT  444                    // total persistent CTAs (3/SM x 148 SMs)
#define NOUT  (NTOT - NREC)          // 188 output-GEMM CTAs
#define XJOBS 512u                   // Xin tiles: 64 mtiles x 8 ntiles

// output jobs: 64x128 logits tiles, t-octet ordering for gW L2 reuse
#define OJOBS     16000u             // 64 t * 250 ntiles
#define OJ_PER_TQ 2000u              // 250 * 8

typedef unsigned long long u64;

__device__ __forceinline__ float sigmf(float x){ return 1.0f/(1.0f + expf(-x)); }

// ---------------- smem / async-copy / mma helpers ----------------
__device__ __forceinline__ uint32_t smem_u32(const void* p){
    uint32_t a;
    asm("{ .reg .u64 t; cvta.to.shared.u64 t, %1; cvt.u32.u64 %0, t; }" : "=r"(a) : "l"(p));
    return a;
}
#define CP16(sa, gp) \
    asm volatile("cp.async.cg.shared.global [%0], [%1], 16;" :: "r"((uint32_t)(sa)), "l"(gp) : "memory")
#define CP_COMMIT() asm volatile("cp.async.commit_group;" ::: "memory")
#define CP_WAIT(n)  asm volatile("cp.async.wait_group %0;" :: "n"(n) : "memory")
#define BARX(id)    asm volatile("bar.sync %0, 128;" :: "r"(id) : "memory")

__device__ __forceinline__ void ldsm4(uint32_t* r, uint32_t addr){
    asm volatile("ldmatrix.sync.aligned.m8n8.x4.shared.b16 {%0,%1,%2,%3}, [%4];"
        : "=r"(r[0]), "=r"(r[1]), "=r"(r[2]), "=r"(r[3]) : "r"(addr));
}
__device__ __forceinline__ void mma_bf16(float* d, const uint32_t* a, const uint32_t* b){
    asm volatile(
        "mma.sync.aligned.m16n8k16.row.col.f32.bf16.bf16.f32 "
        "{%0,%1,%2,%3}, {%4,%5,%6,%7}, {%8,%9}, {%0,%1,%2,%3};"
        : "+f"(d[0]), "+f"(d[1]), "+f"(d[2]), "+f"(d[3])
        : "r"(a[0]), "r"(a[1]), "r"(a[2]), "r"(a[3]), "r"(b[0]), "r"(b[1]));
}

// ---------------- device scratch ----------------
__device__ __align__(16) float g_Xin[SEQL*BH];
__device__ __align__(16) float g_prev0[BH];
__device__ __align__(16) float g_prev1[BH];
__device__ __align__(16) float g_z0[BH];
__device__ __align__(16) float g_z1[BH];
__device__ __align__(16) float g_part[32*BH];
// bf16 hi/lo activation operands
__device__ __align__(16) __nv_bfloat16 b_prev0_h[BH], b_prev0_l[BH];
__device__ __align__(16) __nv_bfloat16 b_prev1_h[BH], b_prev1_l[BH];
__device__ __align__(16) __nv_bfloat16 b_rp0_h[BH],   b_rp0_l[BH];
__device__ __align__(16) __nv_bfloat16 b_rp1_h[BH],   b_rp1_l[BH];
__device__ __align__(16) __nv_bfloat16 b_r0pre_h[BH], b_r0pre_l[BH];
__device__ __align__(16) __nv_bfloat16 b_f0pre_h[BH], b_f0pre_l[BH];
__device__ __align__(16) __nv_bfloat16 b_h0pre_h[BH], b_h0pre_l[BH];
// recurrence weights: 0=Ur0 1=Uf0 2=Uh0 3=Wr1 4=Ur1 5=Wf1 6=Uf1 7=Wh1 8=Uh1
__device__ __align__(16) __nv_bfloat16 gRW_hi[9*HH], gRW_lo[9*HH];
// Xin operands
__device__ __align__(16) __nv_bfloat16 gX_hi[SEQL*BH], gX_lo[SEQL*BH];
__device__ __align__(16) __nv_bfloat16 gWin_hi[HH], gWin_lo[HH];
// output GEMM operands
__device__ __align__(16) __nv_bfloat16 gH_hi[SEQL*BH], gH_lo[SEQL*BH];
__device__ __align__(16) __nv_bfloat16 gW_hi[(size_t)VOCAB*HID], gW_lo[(size_t)VOCAB*HID];

// persistent-kernel coordination (all monotone -> graph-replay safe)
__device__ unsigned g_barCnt = 0;
__device__ volatile unsigned g_barGen = 0;
__device__ unsigned g_barCnt2 = 0;           // out-group barrier (disjoint counters)
__device__ volatile unsigned g_barGen2 = 0;
__device__ unsigned g_tdone   = 0;           // monotone finished-timestep counter
__device__ unsigned g_jobCtr  = 0;           // monotone logits-job claim counter
__device__ unsigned g_xinDone = 0;           // monotone Xin-tile completion counter
__device__ volatile unsigned g_wready = 0;   // monotone gW-split-ready flag

// barrier over `count` CTAs of the rec/entry group (counter set 1)
__device__ __forceinline__ void ctabar(unsigned count){
    __threadfence();
    BARX(1);
    if (threadIdx.x == 0){
        unsigned g = g_barGen;
        if (atomicAdd(&g_barCnt, 1u) == count - 1u){
            g_barCnt = 0;
            __threadfence();
            g_barGen = g + 1u;
        } else {
            while (g_barGen == g) { __nanosleep(32); }
        }
        __threadfence();
    }
    BARX(1);
}
// barrier over the NOUT out-group CTAs (counter set 2)
__device__ __forceinline__ void outbar(){
    __threadfence();
    BARX(1);
    if (threadIdx.x == 0){
        unsigned g = g_barGen2;
        if (atomicAdd(&g_barCnt2, 1u) == (unsigned)NOUT - 1u){
            g_barCnt2 = 0;
            __threadfence();
            g_barGen2 = g + 1u;
        } else {
            while (g_barGen2 == g) { __nanosleep(32); }
        }
        __threadfence();
    }
    BARX(1);
}

__device__ __forceinline__ void split_store4(__nv_bfloat16* hi, __nv_bfloat16* lo, size_t i, float4 v){
    __nv_bfloat162 h0 = __floats2bfloat162_rn(v.x, v.y);
    __nv_bfloat162 h1 = __floats2bfloat162_rn(v.z, v.w);
    __nv_bfloat162 l0 = __floats2bfloat162_rn(v.x - __low2float(h0),  v.y - __high2float(h0));
    __nv_bfloat162 l1 = __floats2bfloat162_rn(v.z - __low2float(h1),  v.w - __high2float(h1));
    *(__nv_bfloat162*)(hi + i)     = h0;
    *(__nv_bfloat162*)(hi + i + 2) = h1;
    *(__nv_bfloat162*)(lo + i)     = l0;
    *(__nv_bfloat162*)(lo + i + 2) = l1;
}
#define V4ADD(a,b) do{ (a).x+=(b).x; (a).y+=(b).y; (a).z+=(b).z; (a).w+=(b).w; }while(0)

// ---------------- shared 64x128 HMMA core ----------------
#define RSTAGE   30720
#define RECSMEM  (2*RSTAGE)                 // 61440
#define TOTSMEM  (RECSMEM + 16)             // + claim slot

__device__ __noinline__ void mma_core64(
    const __nv_bfloat16* __restrict__ Ah, const __nv_bfloat16* __restrict__ Al,
    const __nv_bfloat16* __restrict__ Bh, const __nv_bfloat16* __restrict__ Bl,
    int k0, int kLen,
    float* __restrict__ C, unsigned ldc, int m0, int n0,
    const float* __restrict__ bias)
{
    extern __shared__ __align__(128) char smem[];
    const uint32_t sb = smem_u32(smem);
    const int tid  = threadIdx.x;
    const int lane = tid & 31;
    const int wn   = tid >> 5;

    auto issue = [&](int buf, int kofs){
        uint32_t s0 = sb + buf*RSTAGE;
#pragma unroll
        for (int i = 0; i < 2; i++){
            int idx = tid + i*128, row = idx >> 2, sg = idx & 3;
            uint32_t off = (uint32_t)row*80 + sg*16;
            size_t g = (size_t)row*HID + kofs + sg*8;
            CP16(s0 +        off, Ah + g);
            CP16(s0 + 5120 + off, Al + g);
        }
#pragma unroll
        for (int i = 0; i < 4; i++){
            int idx = tid + i*128, row = idx >> 2, sg = idx & 3;
            uint32_t off = (uint32_t)row*80 + sg*16;
            size_t g = (size_t)row*HID + kofs + sg*8;
            CP16(s0 + 10240 + off, Bh + g);
            CP16(s0 + 20480 + off, Bl + g);
        }
    };

    const int rowA = (lane & 7) + ((lane >> 3) & 1)*8;
    const uint32_t aoff = (uint32_t)rowA*80 + (uint32_t)(lane >> 4)*16;
    const int rowB = (lane & 7) + (lane >> 4)*8;
    const uint32_t boff = 10240u + (uint32_t)(wn*32 + rowB)*80 + (uint32_t)((lane >> 3) & 1)*16;

    float acc[4][4][4];
#pragma unroll
    for (int mi = 0; mi < 4; mi++)
#pragma unroll
        for (int ni = 0; ni < 4; ni++)
#pragma unroll
            for (int r = 0; r < 4; r++) acc[mi][ni][r] = 0.f;

    const int nst = kLen >> 5;
    issue(0, k0); CP_COMMIT();

    for (int s = 0; s < nst; s++){
        if (s + 1 < nst){ issue((s+1)&1, k0 + (s+1)*32); CP_COMMIT(); CP_WAIT(1); }
        else CP_WAIT(0);
        BARX(1);

        const uint32_t st = sb + (s&1)*RSTAGE;
#pragma unroll
        for (int kk = 0; kk < 2; kk++){
            uint32_t aH[4][4], aL[4][4], bH[4][2], bL[4][2];
#pragma unroll
            for (int mi = 0; mi < 4; mi++){
                ldsm4(aH[mi], st +        aoff + mi*(16*80) + kk*32);
                ldsm4(aL[mi], st + 5120 + aoff + mi*(16*80) + kk*32);
            }
#pragma unroll
            for (int p = 0; p < 2; p++){
                uint32_t tr[4];
                ldsm4(tr, st +         boff + p*(16*80) + kk*32);
                bH[2*p][0]=tr[0]; bH[2*p][1]=tr[1]; bH[2*p+1][0]=tr[2]; bH[2*p+1][1]=tr[3];
                ldsm4(tr, st + 10240 + boff + p*(16*80) + kk*32);
                bL[2*p][0]=tr[0]; bL[2*p][1]=tr[1]; bL[2*p+1][0]=tr[2]; bL[2*p+1][1]=tr[3];
            }
#pragma unroll
            for (int mi = 0; mi < 4; mi++)
#pragma unroll
                for (int ni = 0; ni < 4; ni++){
                    mma_bf16(acc[mi][ni], aH[mi], bH[ni]);
                    mma_bf16(acc[mi][ni], aH[mi], bL[ni]);
                    mma_bf16(acc[mi][ni], aL[mi], bH[ni]);
                }
        }
        BARX(1);
    }

    const int mBase = m0 + (lane >> 2);
    const int nBase = n0 + wn*32 + (lane & 3)*2;
    float2 bv[4];
#pragma unroll
    for (int ni = 0; ni < 4; ni++)
        bv[ni] = bias ? *(const float2*)&bias[nBase + ni*8] : make_float2(0.f, 0.f);
#pragma unroll
    for (int mi = 0; mi < 4; mi++)
#pragma unroll
        for (int ni = 0; ni < 4; ni++)
#pragma unroll
            for (int r = 0; r < 2; r++){
                int m = mBase + mi*16 + r*8;
                float2 v = make_float2(acc[mi][ni][2*r] + bv[ni].x,
                                       acc[mi][ni][2*r+1] + bv[ni].y);
                *(float2*)&C[(size_t)m*ldc + nBase + ni*8] = v;
            }
}

// recurrence job bodies -----------------------------------------------------
__device__ __forceinline__ void gates0_body(int nt, int gate, int ks){
    size_t wofs = (size_t)gate*HH + (size_t)nt*128*HID;
    mma_core64(b_prev0_h, b_prev0_l, gRW_hi + wofs, gRW_lo + wofs,
               ks*128, 128, g_part + (size_t)(16 + gate*8 + ks)*BH, HID, 0, nt*128, nullptr);
}
__device__ __forceinline__ void last_body(int nt, int ks){
    const __nv_bfloat16 *Ah, *Al; int widx, k0;
    if (ks < 8){ Ah = b_h0pre_h; Al = b_h0pre_l; widx = 7; k0 = ks*128; }
    else       { Ah = b_rp1_h;   Al = b_rp1_l;   widx = 8; k0 = (ks-8)*128; }
    size_t wofs = (size_t)widx*HH + (size_t)nt*128*HID;
    mma_core64(Ah, Al, gRW_hi + wofs, gRW_lo + wofs,
               k0, 128, g_part + (size_t)ks*BH, HID, 0, nt*128, nullptr);
}
__device__ __forceinline__ void mid_job(int j){
    int job = j >> 6;
    int r   = j & 63;
    int nt  = r & 7;
    int ks  = r >> 3;
    const __nv_bfloat16 *Ah, *Al; int widx, k0, kLen;
    if (job == 0){ Ah = b_rp0_h; Al = b_rp0_l; widx = 2; k0 = ks*128; kLen = 128; }
    else {
        int wW = (job == 1) ? 3 : 5;
        int wU = (job == 1) ? 4 : 6;
        if (ks < 4){
            Ah = (job == 1) ? b_r0pre_h : b_f0pre_h;
            Al = (job == 1) ? b_r0pre_l : b_f0pre_l;
            widx = wW; k0 = ks*256;
        } else {
            Ah = b_prev1_h; Al = b_prev1_l;
            widx = wU; k0 = (ks-4)*256;
        }
        kLen = 256;
    }
    size_t wofs = (size_t)widx*HH + (size_t)nt*128*HID;
    mma_core64(Ah, Al, gRW_hi + wofs, gRW_lo + wofs,
               k0, kLen, g_part + (size_t)(job*8 + ks)*BH, HID, 0, nt*128, nullptr);
}

// output worker: claim 64x128 logits tiles, wait for step readiness, compute
__device__ void out_worker(unsigned jobs_base, unsigned tdone_base,
                           const float* __restrict__ outb, float* __restrict__ logits)
{
    extern __shared__ __align__(128) char smem[];
    unsigned* claim = (unsigned*)(smem + RECSMEM);
    const int tid = threadIdx.x;
    for (;;){
        if (tid == 0) *claim = atomicAdd(&g_jobCtr, 1u) - jobs_base;
        BARX(1);
        unsigned j = *claim;
        if (j >= OJOBS) break;
        unsigned tq  = j / OJ_PER_TQ;
        unsigned rem = j - tq*OJ_PER_TQ;
        unsigned nt  = rem >> 3;
        unsigned t   = tq*8u + (rem & 7u);
        if (tid == 0){
            while (*(volatile unsigned*)&g_tdone < tdone_base + t + 1u) __nanosleep(64);
        }
        BARX(1);
        mma_core64(gH_hi + (size_t)t*BH, gH_lo + (size_t)t*BH,
                   gW_hi + (size_t)nt*128*HID, gW_lo + (size_t)nt*128*HID,
                   0, HID, logits, VOCAB, (int)(t*64u), (int)(nt*128u), outb);
    }
}

// fin device functions (1 float4 item per active thread; __ldcg bypasses stale L1)
__device__ __forceinline__ void fin0_one(size_t i, int t,
                                         const float* br0, const float* bf0){
    int n = (int)(i & (HID-1));
    float4 s0 = make_float4(0,0,0,0), s1 = s0;
#pragma unroll
    for (int ks = 0; ks < 8; ks++){
        float4 a = __ldcg((const float4*)&g_part[(size_t)(16+ks)*BH + i]); V4ADD(s0, a);
        float4 b = __ldcg((const float4*)&g_part[(size_t)(24+ks)*BH + i]); V4ADD(s1, b);
    }
    float4 xv = __ldcg((const float4*)&g_Xin[(size_t)t*BH + i]);
    float4 bR = *(const float4*)&br0[n];
    float4 bF = *(const float4*)&bf0[n];
    float4 p0 = __ldcg((const float4*)&g_prev0[i]);
    float4 rp = make_float4(xv.x+bR.x+s0.x, xv.y+bR.y+s0.y, xv.z+bR.z+s0.z, xv.w+bR.w+s0.w);
    float4 fp = make_float4(xv.x+bF.x+s1.x, xv.y+bF.y+s1.y, xv.z+bF.z+s1.z, xv.w+bF.w+s1.w);
    split_store4(b_r0pre_h, b_r0pre_l, i, rp);
    split_store4(b_f0pre_h, b_f0pre_l, i, fp);
    float4 rpv = make_float4(sigmf(rp.x)*p0.x, sigmf(rp.y)*p0.y, sigmf(rp.z)*p0.z, sigmf(rp.w)*p0.w);
    split_store4(b_rp0_h, b_rp0_l, i, rpv);
    *(float4*)&g_z0[i] = make_float4(sigmf(fp.x), sigmf(fp.y), sigmf(fp.z), sigmf(fp.w));
}

__device__ __forceinline__ void fin_mid_one(size_t i, int t, const float* bh0,
                                            const float* br1, const float* bf1){
    int n = (int)(i & (HID-1));
    float4 s0 = make_float4(0,0,0,0), s1 = s0, s2 = s0;
#pragma unroll
    for (int ks = 0; ks < 8; ks++){
        float4 a = __ldcg((const float4*)&g_part[(size_t)ks*BH + i]);      V4ADD(s0, a);
        float4 b = __ldcg((const float4*)&g_part[(size_t)(8+ks)*BH + i]);  V4ADD(s1, b);
        float4 c = __ldcg((const float4*)&g_part[(size_t)(16+ks)*BH + i]); V4ADD(s2, c);
    }
    float4 xv = __ldcg((const float4*)&g_Xin[(size_t)t*BH + i]);
    float4 bH = *(const float4*)&bh0[n];
    float4 ht = make_float4(xv.x+bH.x+s0.x, xv.y+bH.y+s0.y, xv.z+bH.z+s0.z, xv.w+bH.w+s0.w);
    float4 z  = __ldcg((const float4*)&g_z0[i]);
    float4 p0 = __ldcg((const float4*)&g_prev0[i]);
    float4 h0 = make_float4((1.f-z.x)*p0.x + z.x*tanhf(ht.x),
                            (1.f-z.y)*p0.y + z.y*tanhf(ht.y),
                            (1.f-z.z)*p0.z + z.z*tanhf(ht.z),
                            (1.f-z.w)*p0.w + z.w*tanhf(ht.w));
    *(float4*)&g_prev0[i] = h0;
    split_store4(b_prev0_h, b_prev0_l, i, h0);
    split_store4(b_h0pre_h, b_h0pre_l, i, ht);
    float4 bR = *(const float4*)&br1[n];
    float4 bF = *(const float4*)&bf1[n];
    float4 p1 = __ldcg((const float4*)&g_prev1[i]);
    float4 rp1 = make_float4(sigmf(s1.x+bR.x)*p1.x, sigmf(s1.y+bR.y)*p1.y,
                             sigmf(s1.z+bR.z)*p1.z, sigmf(s1.w+bR.w)*p1.w);
    split_store4(b_rp1_h, b_rp1_l, i, rp1);
    *(float4*)&g_z1[i] = make_float4(sigmf(s2.x+bF.x), sigmf(s2.y+bF.y),
                                     sigmf(s2.z+bF.z), sigmf(s2.w+bF.w));
}

__device__ __forceinline__ void finB_one(size_t i, int t, int dogates,
                                         const float* bh1, const float* br0, const float* bf0){
    int n = (int)(i & (HID-1));
    float4 s = make_float4(0,0,0,0);
#pragma unroll
    for (int ks = 0; ks < 16; ks++){
        float4 a = __ldcg((const float4*)&g_part[(size_t)ks*BH + i]); V4ADD(s, a);
    }
    float4 bH = *(const float4*)&bh1[n];
    float4 z  = __ldcg((const float4*)&g_z1[i]);
    float4 p1 = __ldcg((const float4*)&g_prev1[i]);
    float4 h1 = make_float4((1.f-z.x)*p1.x + z.x*tanhf(s.x+bH.x),
                            (1.f-z.y)*p1.y + z.y*tanhf(s.y+bH.y),
                            (1.f-z.z)*p1.z + z.z*tanhf(s.z+bH.z),
                            (1.f-z.w)*p1.w + z.w*tanhf(s.w+bH.w));
    *(float4*)&g_prev1[i] = h1;
    split_store4(b_prev1_h, b_prev1_l, i, h1);
    split_store4(gH_hi, gH_lo, (size_t)t*BH + i, h1);
    if (dogates){
        float4 s0 = make_float4(0,0,0,0), s1 = s0;
#pragma unroll
        for (int ks = 0; ks < 8; ks++){
            float4 a = __ldcg((const float4*)&g_part[(size_t)(16+ks)*BH + i]); V4ADD(s0, a);
            float4 b = __ldcg((const float4*)&g_part[(size_t)(24+ks)*BH + i]); V4ADD(s1, b);
        }
        float4 xv = __ldcg((const float4*)&g_Xin[(size_t)(t+1)*BH + i]);
        float4 bR = *(const float4*)&br0[n];
        float4 bF = *(const float4*)&bf0[n];
        float4 p0 = __ldcg((const float4*)&g_prev0[i]);
        float4 rp = make_float4(xv.x+bR.x+s0.x, xv.y+bR.y+s0.y, xv.z+bR.z+s0.z, xv.w+bR.w+s0.w);
        float4 fp = make_float4(xv.x+bF.x+s1.x, xv.y+bF.y+s1.y, xv.z+bF.z+s1.z, xv.w+bF.w+s1.w);
        split_store4(b_r0pre_h, b_r0pre_l, i, rp);
        split_store4(b_f0pre_h, b_f0pre_l, i, fp);
        float4 rpv = make_float4(sigmf(rp.x)*p0.x, sigmf(rp.y)*p0.y, sigmf(rp.z)*p0.z, sigmf(rp.w)*p0.w);
        split_store4(b_rp0_h, b_rp0_l, i, rpv);
        *(float4*)&g_z0[i] = make_float4(sigmf(fp.x), sigmf(fp.y), sigmf(fp.z), sigmf(fp.w));
    }
}

// ---------------- fully-fused persistent kernel ----------------
__global__ void __launch_bounds__(128,3) k_recur(
    const int*   __restrict__ toks, const float* __restrict__ hid,
    const float* __restrict__ emb,  const float* __restrict__ Win,
    const float* __restrict__ Wr1,  const float* __restrict__ Wf1,
    const float* __restrict__ Wh1,  const float* __restrict__ Ur,
    const float* __restrict__ Uf,   const float* __restrict__ Uh,
    const float* __restrict__ br0, const float* __restrict__ bf0,
    const float* __restrict__ bh0, const float* __restrict__ br1,
    const float* __restrict__ bf1, const float* __restrict__ bh1,
    const float* __restrict__ outW,
    const float* __restrict__ outb, float* __restrict__ logits)
{
    const int b   = blockIdx.x;
    const int tid = threadIdx.x;
    const size_t gtid = (size_t)b*128 + tid;
    const size_t GS   = (size_t)NTOT*128;

    // per-invocation bases (previous invocation fully finished -> stable)
    unsigned tdone_base = *(volatile unsigned*)&g_tdone;
    unsigned jobs_base  = *(volatile unsigned*)&g_jobCtr;
    unsigned xin_base   = *(volatile unsigned*)&g_xinDone;
    unsigned wr_base    = *(volatile unsigned*)&g_wready;

    // ---- common prologue: all conversions, grid-strided over all CTAs ----
    // 1) hidden-state init + split
    for (size_t i = gtid; i < 2*(size_t)BH; i += GS){
        float v = hid[i];
        if (i < BH){
            g_prev0[i] = v;
            __nv_bfloat16 h = __float2bfloat16_rn(v);
            b_prev0_h[i] = h; b_prev0_l[i] = __float2bfloat16_rn(v - __bfloat162float(h));
        } else {
            size_t j = i - BH;
            g_prev1[j] = v;
            __nv_bfloat16 h = __float2bfloat16_rn(v);
            b_prev1_h[j] = h; b_prev1_l[j] = __float2bfloat16_rn(v - __bfloat162float(h));
        }
    }
    // 2) Win split
    for (size_t i4 = gtid; i4 < (size_t)HH/4; i4 += GS)
        split_store4(gWin_hi, gWin_lo, i4*4, *(const float4*)(Win + i4*4));
    // 3) 9 recurrence weights split
    {
        const float* srcs[9] = {Ur, Uf, Uh, Wr1, Ur + HH, Wf1, Uf + HH, Wh1, Uh + HH};
        for (size_t i4 = gtid; i4 < 9*((size_t)HH/4); i4 += GS){
            size_t m = i4 >> 18;                 // HH/4 = 262144 = 2^18
            size_t r = i4 & 262143u;
            split_store4(gRW_hi, gRW_lo, m*HH + r*4, *(const float4*)(srcs[m] + r*4));
        }
    }
    // 4) X gather + scale + split
    for (size_t i4 = gtid; i4 < (size_t)SEQL*BATCH*EMBD/4; i4 += GS){
        int row  = (int)(i4 >> 8);
        int colq = (int)(i4 & 255);
        int tok  = toks[row];
        float4 v = *(const float4*)(emb + (size_t)tok*EMBD + colq*4);
        v.x *= SQRTE; v.y *= SQRTE; v.z *= SQRTE; v.w *= SQRTE;
        split_store4(gX_hi, gX_lo, i4*4, v);
    }
    ctabar(NTOT);   // all conversions visible everywhere

    if (b >= NREC){
        // ---- out-group: Xin tiles (static), then gW split, then logits pool ----
        for (unsigned j = (unsigned)(b - NREC); j < XJOBS; j += (unsigned)NOUT){
            unsigned mt = j >> 3, nt = j & 7u;
            mma_core64(gX_hi + (size_t)mt*64*HID, gX_lo + (size_t)mt*64*HID,
                       gWin_hi + (size_t)nt*128*HID, gWin_lo + (size_t)nt*128*HID,
                       0, HID, g_Xin, HID, (int)(mt*64u), (int)(nt*128u), nullptr);
            __threadfence();
            BARX(1);
            if (tid == 0) atomicAdd(&g_xinDone, 1u);
        }
        // gW split (overlaps rec steps)
        for (size_t i4 = (size_t)(b - NREC)*128 + tid; i4 < (size_t)VOCAB*HID/4; i4 += (size_t)NOUT*128)
            split_store4(gW_hi, gW_lo, i4*4, *(const float4*)(outW + i4*4));
        outbar();
        if (b == NREC && tid == 0){
            __threadfence();
            *(volatile unsigned*)&g_wready = wr_base + 1u;
        }
        out_worker(jobs_base, tdone_base, outb, logits);
        return;
    }

    // ---- recurrence CTA ----
    const bool finT = (tid < 64);
    const size_t item = ((size_t)b*64 + tid)*4;

    if (b < 128) gates0_body((b>>3)&7, b>>6, b&7);
    ctabar(NREC);
    // wait until all Xin tiles are written (fin0 reads g_Xin)
    if (tid == 0){
        while (*(volatile unsigned*)&g_xinDone < xin_base + XJOBS) __nanosleep(64);
        __threadfence();
    }
    BARX(1);
    if (finT) fin0_one(item, 0, br0, bf0);
    ctabar(NREC);

    for (int t = 0; t < SEQL; t++){
        if (b < 192) mid_job(b);
        ctabar(NREC);
        if (finT) fin_mid_one(item, t, bh0, br1, bf1);
        ctabar(NREC);
        if (b < 128) last_body(b >> 4, b & 15);
        else if (t < SEQL-1){
            int r = b - 128;
            gates0_body((r>>3)&7, r>>6, r&7);
        }
        ctabar(NREC);
        if (finT) finB_one(item, t, (t < SEQL-1) ? 1 : 0, bh1, br0, bf0);
        ctabar(NREC);
        if (b == 0 && tid == 0)
            *(volatile unsigned*)&g_tdone = tdone_base + (unsigned)(t + 1);
    }

    // join logits pool (guard: gW split complete)
    if (tid == 0){
        while (*(volatile unsigned*)&g_wready < wr_base + 1u) __nanosleep(64);
        __threadfence();
    }
    BARX(1);
    out_worker(jobs_base, tdone_base, outb, logits);
}

// final hidden-state copy
__global__ void k_copy(float* __restrict__ dst){
    int i = blockIdx.x*blockDim.x + threadIdx.x;
    dst[i] = (i < BH) ? g_prev0[i] : g_prev1[i - BH];
}

// ---------------- launch ----------------
extern "C" void kernel_launch(void* const* d_in, const int* in_sizes, int n_in,
                              void* d_out, int out_size) {
    const int*   toks = (const int*)  d_in[0];
    const float* hid  = (const float*)d_in[1];
    const float* emb  = (const float*)d_in[2];
    const float* Win  = (const float*)d_in[3];
    const float* Wr1  = (const float*)d_in[4];
    const float* Wf1  = (const float*)d_in[5];
    const float* Wh1  = (const float*)d_in[6];
    const float* Ur   = (const float*)d_in[7];
    const float* br   = (const float*)d_in[8];
    const float* Uf   = (const float*)d_in[9];
    const float* bf   = (const float*)d_in[10];
    const float* Uh   = (const float*)d_in[11];
    const float* bh   = (const float*)d_in[12];
    const float* outW = (const float*)d_in[13];
    const float* outb = (const float*)d_in[14];
    float* out = (float*)d_out;

    cudaFuncSetAttribute(k_recur, cudaFuncAttributeMaxDynamicSharedMemorySize, TOTSMEM);

    // ONE persistent kernel does everything except the final state copy
    k_recur<<<NTOT, 128, TOTSMEM>>>(toks, hid, emb, Win, Wr1, Wf1, Wh1, Ur, Uf, Uh,
                                    br, bf, bh, br + HID, bf + HID, bh + HID,
                                    outW, outb, out);

    if ((size_t)out_size >= LOGITS_N + 2*(size_t)BH)
        k_copy<<<2*BH/256, 256>>>(out + LOGITS_N);
}

// round 16
// speedup vs baseline: 1.4899x; 1.0127x over previous
#include <cuda_runtime.h>
#include <cuda_bf16.h>
#include <math.h>
#include <stdint.h>

// ---------------- problem constants ----------------
#define SEQL  64
#define BATCH 64
#define HID   1024
#define EMBD  1024
#define VOCAB 32000
#define BH    (BATCH*HID)            // 65536
#define LOGITS_N ((size_t)SEQL*BATCH*VOCAB)
#define SQRTE 32.0f
#define HH    (HID*HID)
#define NREC  256                    // recurrence CTAs
#define NTOT  444                    // total persistent CTAs (3/SM x 148 SMs)
#define NOUT  (NTOT - NREC)          // 188 output-GEMM CTAs
#define XJOBS 512u                   // Xin tiles: 64 t x 8 ntiles (t-major)

// output jobs: 64x128 logits tiles, t-octet ordering for gW L2 reuse
#define OJOBS     16000u             // 64 t * 250 ntiles
#define OJ_PER_TQ 2000u              // 250 * 8

typedef unsigned long long u64;

__device__ __forceinline__ float sigmf(float x){ return 1.0f/(1.0f + expf(-x)); }

// ---------------- smem / async-copy / mma helpers ----------------
__device__ __forceinline__ uint32_t smem_u32(const void* p){
    uint32_t a;
    asm("{ .reg .u64 t; cvta.to.shared.u64 t, %1; cvt.u32.u64 %0, t; }" : "=r"(a) : "l"(p));
    return a;
}
#define CP16(sa, gp) \
    asm volatile("cp.async.cg.shared.global [%0], [%1], 16;" :: "r"((uint32_t)(sa)), "l"(gp) : "memory")
#define CP_COMMIT() asm volatile("cp.async.commit_group;" ::: "memory")
#define CP_WAIT(n)  asm volatile("cp.async.wait_group %0;" :: "n"(n) : "memory")
#define BARX(id)    asm volatile("bar.sync %0, 128;" :: "r"(id) : "memory")

__device__ __forceinline__ void ldsm4(uint32_t* r, uint32_t addr){
    asm volatile("ldmatrix.sync.aligned.m8n8.x4.shared.b16 {%0,%1,%2,%3}, [%4];"
        : "=r"(r[0]), "=r"(r[1]), "=r"(r[2]), "=r"(r[3]) : "r"(addr));
}
__device__ __forceinline__ void mma_bf16(float* d, const uint32_t* a, const uint32_t* b){
    asm volatile(
        "mma.sync.aligned.m16n8k16.row.col.f32.bf16.bf16.f32 "
        "{%0,%1,%2,%3}, {%4,%5,%6,%7}, {%8,%9}, {%0,%1,%2,%3};"
        : "+f"(d[0]), "+f"(d[1]), "+f"(d[2]), "+f"(d[3])
        : "r"(a[0]), "r"(a[1]), "r"(a[2]), "r"(a[3]), "r"(b[0]), "r"(b[1]));
}

// ---------------- device scratch ----------------
__device__ __align__(16) float g_Xin[SEQL*BH];
__device__ __align__(16) float g_prev0[BH];
__device__ __align__(16) float g_prev1[BH];
__device__ __align__(16) float g_z0[BH];
__device__ __align__(16) float g_z1[BH];
__device__ __align__(16) float g_part[32*BH];
// bf16 hi/lo activation operands
__device__ __align__(16) __nv_bfloat16 b_prev0_h[BH], b_prev0_l[BH];
__device__ __align__(16) __nv_bfloat16 b_prev1_h[BH], b_prev1_l[BH];
__device__ __align__(16) __nv_bfloat16 b_rp0_h[BH],   b_rp0_l[BH];
__device__ __align__(16) __nv_bfloat16 b_rp1_h[BH],   b_rp1_l[BH];
__device__ __align__(16) __nv_bfloat16 b_r0pre_h[BH], b_r0pre_l[BH];
__device__ __align__(16) __nv_bfloat16 b_f0pre_h[BH], b_f0pre_l[BH];
__device__ __align__(16) __nv_bfloat16 b_h0pre_h[BH], b_h0pre_l[BH];
// recurrence weights: 0=Ur0 1=Uf0 2=Uh0 3=Wr1 4=Ur1 5=Wf1 6=Uf1 7=Wh1 8=Uh1
__device__ __align__(16) __nv_bfloat16 gRW_hi[9*HH], gRW_lo[9*HH];
// Xin operands
__device__ __align__(16) __nv_bfloat16 gX_hi[SEQL*BH], gX_lo[SEQL*BH];
__device__ __align__(16) __nv_bfloat16 gWin_hi[HH], gWin_lo[HH];
// output GEMM operands
__device__ __align__(16) __nv_bfloat16 gH_hi[SEQL*BH], gH_lo[SEQL*BH];
__device__ __align__(16) __nv_bfloat16 gW_hi[(size_t)VOCAB*HID], gW_lo[(size_t)VOCAB*HID];

// persistent-kernel coordination (all monotone -> graph-replay safe)
__device__ unsigned g_barCnt = 0;
__device__ volatile unsigned g_barGen = 0;
__device__ unsigned g_barCnt2 = 0;           // out-group barrier (disjoint counters)
__device__ volatile unsigned g_barGen2 = 0;
__device__ unsigned g_tdone   = 0;           // monotone finished-timestep counter
__device__ unsigned g_jobCtr  = 0;           // monotone logits-job claim counter
__device__ unsigned g_xinT[SEQL] = {0};      // monotone per-timestep Xin-tile counters
__device__ volatile unsigned g_wready = 0;   // monotone gW-split-ready flag

// barrier over `count` CTAs of the rec/entry group (counter set 1)
__device__ __forceinline__ void ctabar(unsigned count){
    __threadfence();
    BARX(1);
    if (threadIdx.x == 0){
        unsigned g = g_barGen;
        if (atomicAdd(&g_barCnt, 1u) == count - 1u){
            g_barCnt = 0;
            __threadfence();
            g_barGen = g + 1u;
        } else {
            while (g_barGen == g) { __nanosleep(32); }
        }
        __threadfence();
    }
    BARX(1);
}
// barrier over the NOUT out-group CTAs (counter set 2)
__device__ __forceinline__ void outbar(){
    __threadfence();
    BARX(1);
    if (threadIdx.x == 0){
        unsigned g = g_barGen2;
        if (atomicAdd(&g_barCnt2, 1u) == (unsigned)NOUT - 1u){
            g_barCnt2 = 0;
            __threadfence();
            g_barGen2 = g + 1u;
        } else {
            while (g_barGen2 == g) { __nanosleep(32); }
        }
        __threadfence();
    }
    BARX(1);
}

__device__ __forceinline__ void split_store4(__nv_bfloat16* hi, __nv_bfloat16* lo, size_t i, float4 v){
    __nv_bfloat162 h0 = __floats2bfloat162_rn(v.x, v.y);
    __nv_bfloat162 h1 = __floats2bfloat162_rn(v.z, v.w);
    __nv_bfloat162 l0 = __floats2bfloat162_rn(v.x - __low2float(h0),  v.y - __high2float(h0));
    __nv_bfloat162 l1 = __floats2bfloat162_rn(v.z - __low2float(h1),  v.w - __high2float(h1));
    *(__nv_bfloat162*)(hi + i)     = h0;
    *(__nv_bfloat162*)(hi + i + 2) = h1;
    *(__nv_bfloat162*)(lo + i)     = l0;
    *(__nv_bfloat162*)(lo + i + 2) = l1;
}
#define V4ADD(a,b) do{ (a).x+=(b).x; (a).y+=(b).y; (a).z+=(b).z; (a).w+=(b).w; }while(0)

// ---------------- shared 64x128 HMMA core ----------------
#define RSTAGE   30720
#define RECSMEM  (2*RSTAGE)                 // 61440
#define TOTSMEM  (RECSMEM + 16 + SEQL*4)    // + claim slot + xin base snapshot

__device__ __noinline__ void mma_core64(
    const __nv_bfloat16* __restrict__ Ah, const __nv_bfloat16* __restrict__ Al,
    const __nv_bfloat16* __restrict__ Bh, const __nv_bfloat16* __restrict__ Bl,
    int k0, int kLen,
    float* __restrict__ C, unsigned ldc, int m0, int n0,
    const float* __restrict__ bias)
{
    extern __shared__ __align__(128) char smem[];
    const uint32_t sb = smem_u32(smem);
    const int tid  = threadIdx.x;
    const int lane = tid & 31;
    const int wn   = tid >> 5;

    auto issue = [&](int buf, int kofs){
        uint32_t s0 = sb + buf*RSTAGE;
#pragma unroll
        for (int i = 0; i < 2; i++){
            int idx = tid + i*128, row = idx >> 2, sg = idx & 3;
            uint32_t off = (uint32_t)row*80 + sg*16;
            size_t g = (size_t)row*HID + kofs + sg*8;
            CP16(s0 +        off, Ah + g);
            CP16(s0 + 5120 + off, Al + g);
        }
#pragma unroll
        for (int i = 0; i < 4; i++){
            int idx = tid + i*128, row = idx >> 2, sg = idx & 3;
            uint32_t off = (uint32_t)row*80 + sg*16;
            size_t g = (size_t)row*HID + kofs + sg*8;
            CP16(s0 + 10240 + off, Bh + g);
            CP16(s0 + 20480 + off, Bl + g);
        }
    };

    const int rowA = (lane & 7) + ((lane >> 3) & 1)*8;
    const uint32_t aoff = (uint32_t)rowA*80 + (uint32_t)(lane >> 4)*16;
    const int rowB = (lane & 7) + (lane >> 4)*8;
    const uint32_t boff = 10240u + (uint32_t)(wn*32 + rowB)*80 + (uint32_t)((lane >> 3) & 1)*16;

    float acc[4][4][4];
#pragma unroll
    for (int mi = 0; mi < 4; mi++)
#pragma unroll
        for (int ni = 0; ni < 4; ni++)
#pragma unroll
            for (int r = 0; r < 4; r++) acc[mi][ni][r] = 0.f;

    const int nst = kLen >> 5;
    issue(0, k0); CP_COMMIT();

    for (int s = 0; s < nst; s++){
        if (s + 1 < nst){ issue((s+1)&1, k0 + (s+1)*32); CP_COMMIT(); CP_WAIT(1); }
        else CP_WAIT(0);
        BARX(1);

        const uint32_t st = sb + (s&1)*RSTAGE;
#pragma unroll
        for (int kk = 0; kk < 2; kk++){
            uint32_t aH[4][4], aL[4][4], bH[4][2], bL[4][2];
#pragma unroll
            for (int mi = 0; mi < 4; mi++){
                ldsm4(aH[mi], st +        aoff + mi*(16*80) + kk*32);
                ldsm4(aL[mi], st + 5120 + aoff + mi*(16*80) + kk*32);
            }
#pragma unroll
            for (int p = 0; p < 2; p++){
                uint32_t tr[4];
                ldsm4(tr, st +         boff + p*(16*80) + kk*32);
                bH[2*p][0]=tr[0]; bH[2*p][1]=tr[1]; bH[2*p+1][0]=tr[2]; bH[2*p+1][1]=tr[3];
                ldsm4(tr, st + 10240 + boff + p*(16*80) + kk*32);
                bL[2*p][0]=tr[0]; bL[2*p][1]=tr[1]; bL[2*p+1][0]=tr[2]; bL[2*p+1][1]=tr[3];
            }
#pragma unroll
            for (int mi = 0; mi < 4; mi++)
#pragma unroll
                for (int ni = 0; ni < 4; ni++){
                    mma_bf16(acc[mi][ni], aH[mi], bH[ni]);
                    mma_bf16(acc[mi][ni], aH[mi], bL[ni]);
                    mma_bf16(acc[mi][ni], aL[mi], bH[ni]);
                }
        }
        BARX(1);
    }

    const int mBase = m0 + (lane >> 2);
    const int nBase = n0 + wn*32 + (lane & 3)*2;
    float2 bv[4];
#pragma unroll
    for (int ni = 0; ni < 4; ni++)
        bv[ni] = bias ? *(const float2*)&bias[nBase + ni*8] : make_float2(0.f, 0.f);
#pragma unroll
    for (int mi = 0; mi < 4; mi++)
#pragma unroll
        for (int ni = 0; ni < 4; ni++)
#pragma unroll
            for (int r = 0; r < 2; r++){
                int m = mBase + mi*16 + r*8;
                float2 v = make_float2(acc[mi][ni][2*r] + bv[ni].x,
                                       acc[mi][ni][2*r+1] + bv[ni].y);
                *(float2*)&C[(size_t)m*ldc + nBase + ni*8] = v;
            }
}

// recurrence job bodies -----------------------------------------------------
__device__ __forceinline__ void gates0_body(int nt, int gate, int ks){
    size_t wofs = (size_t)gate*HH + (size_t)nt*128*HID;
    mma_core64(b_prev0_h, b_prev0_l, gRW_hi + wofs, gRW_lo + wofs,
               ks*128, 128, g_part + (size_t)(16 + gate*8 + ks)*BH, HID, 0, nt*128, nullptr);
}
__device__ __forceinline__ void last_body(int nt, int ks){
    const __nv_bfloat16 *Ah, *Al; int widx, k0;
    if (ks < 8){ Ah = b_h0pre_h; Al = b_h0pre_l; widx = 7; k0 = ks*128; }
    else       { Ah = b_rp1_h;   Al = b_rp1_l;   widx = 8; k0 = (ks-8)*128; }
    size_t wofs = (size_t)widx*HH + (size_t)nt*128*HID;
    mma_core64(Ah, Al, gRW_hi + wofs, gRW_lo + wofs,
               k0, 128, g_part + (size_t)ks*BH, HID, 0, nt*128, nullptr);
}
__device__ __forceinline__ void mid_job(int j){
    int job = j >> 6;
    int r   = j & 63;
    int nt  = r & 7;
    int ks  = r >> 3;
    const __nv_bfloat16 *Ah, *Al; int widx, k0, kLen;
    if (job == 0){ Ah = b_rp0_h; Al = b_rp0_l; widx = 2; k0 = ks*128; kLen = 128; }
    else {
        int wW = (job == 1) ? 3 : 5;
        int wU = (job == 1) ? 4 : 6;
        if (ks < 4){
            Ah = (job == 1) ? b_r0pre_h : b_f0pre_h;
            Al = (job == 1) ? b_r0pre_l : b_f0pre_l;
            widx = wW; k0 = ks*256;
        } else {
            Ah = b_prev1_h; Al = b_prev1_l;
            widx = wU; k0 = (ks-4)*256;
        }
        kLen = 256;
    }
    size_t wofs = (size_t)widx*HH + (size_t)nt*128*HID;
    mma_core64(Ah, Al, gRW_hi + wofs, gRW_lo + wofs,
               k0, kLen, g_part + (size_t)(job*8 + ks)*BH, HID, 0, nt*128, nullptr);
}

// output worker: claim 64x128 logits tiles, wait for step readiness, compute
__device__ void out_worker(unsigned jobs_base, unsigned tdone_base,
                           const float* __restrict__ outb, float* __restrict__ logits)
{
    extern __shared__ __align__(128) char smem[];
    unsigned* claim = (unsigned*)(smem + RECSMEM);
    const int tid = threadIdx.x;
    for (;;){
        if (tid == 0){
            unsigned j = atomicAdd(&g_jobCtr, 1u) - jobs_base;
            if (j < OJOBS){
                unsigned t = (j / OJ_PER_TQ)*8u + (j % OJ_PER_TQ & 7u);
                while (*(volatile unsigned*)&g_tdone < tdone_base + t + 1u) __nanosleep(64);
            }
            *claim = j;
        }
        BARX(1);
        unsigned j = *claim;
        if (j >= OJOBS) break;
        unsigned tq  = j / OJ_PER_TQ;
        unsigned rem = j - tq*OJ_PER_TQ;
        unsigned nt  = rem >> 3;
        unsigned t   = tq*8u + (rem & 7u);
        mma_core64(gH_hi + (size_t)t*BH, gH_lo + (size_t)t*BH,
                   gW_hi + (size_t)nt*128*HID, gW_lo + (size_t)nt*128*HID,
                   0, HID, logits, VOCAB, (int)(t*64u), (int)(nt*128u), outb);
    }
}

// fin device functions (1 float4 item per active thread; __ldcg bypasses stale L1)
__device__ __forceinline__ void fin0_one(size_t i, int t,
                                         const float* br0, const float* bf0){
    int n = (int)(i & (HID-1));
    float4 s0 = make_float4(0,0,0,0), s1 = s0;
#pragma unroll
    for (int ks = 0; ks < 8; ks++){
        float4 a = __ldcg((const float4*)&g_part[(size_t)(16+ks)*BH + i]); V4ADD(s0, a);
        float4 b = __ldcg((const float4*)&g_part[(size_t)(24+ks)*BH + i]); V4ADD(s1, b);
    }
    float4 xv = __ldcg((const float4*)&g_Xin[(size_t)t*BH + i]);
    float4 bR = *(const float4*)&br0[n];
    float4 bF = *(const float4*)&bf0[n];
    float4 p0 = __ldcg((const float4*)&g_prev0[i]);
    float4 rp = make_float4(xv.x+bR.x+s0.x, xv.y+bR.y+s0.y, xv.z+bR.z+s0.z, xv.w+bR.w+s0.w);
    float4 fp = make_float4(xv.x+bF.x+s1.x, xv.y+bF.y+s1.y, xv.z+bF.z+s1.z, xv.w+bF.w+s1.w);
    split_store4(b_r0pre_h, b_r0pre_l, i, rp);
    split_store4(b_f0pre_h, b_f0pre_l, i, fp);
    float4 rpv = make_float4(sigmf(rp.x)*p0.x, sigmf(rp.y)*p0.y, sigmf(rp.z)*p0.z, sigmf(rp.w)*p0.w);
    split_store4(b_rp0_h, b_rp0_l, i, rpv);
    *(float4*)&g_z0[i] = make_float4(sigmf(fp.x), sigmf(fp.y), sigmf(fp.z), sigmf(fp.w));
}

__device__ __forceinline__ void fin_mid_one(size_t i, int t, const float* bh0,
                                            const float* br1, const float* bf1){
    int n = (int)(i & (HID-1));
    float4 s0 = make_float4(0,0,0,0), s1 = s0, s2 = s0;
#pragma unroll
    for (int ks = 0; ks < 8; ks++){
        float4 a = __ldcg((const float4*)&g_part[(size_t)ks*BH + i]);      V4ADD(s0, a);
        float4 b = __ldcg((const float4*)&g_part[(size_t)(8+ks)*BH + i]);  V4ADD(s1, b);
        float4 c = __ldcg((const float4*)&g_part[(size_t)(16+ks)*BH + i]); V4ADD(s2, c);
    }
    float4 xv = __ldcg((const float4*)&g_Xin[(size_t)t*BH + i]);
    float4 bH = *(const float4*)&bh0[n];
    float4 ht = make_float4(xv.x+bH.x+s0.x, xv.y+bH.y+s0.y, xv.z+bH.z+s0.z, xv.w+bH.w+s0.w);
    float4 z  = __ldcg((const float4*)&g_z0[i]);
    float4 p0 = __ldcg((const float4*)&g_prev0[i]);
    float4 h0 = make_float4((1.f-z.x)*p0.x + z.x*tanhf(ht.x),
                            (1.f-z.y)*p0.y + z.y*tanhf(ht.y),
                            (1.f-z.z)*p0.z + z.z*tanhf(ht.z),
                            (1.f-z.w)*p0.w + z.w*tanhf(ht.w));
    *(float4*)&g_prev0[i] = h0;
    split_store4(b_prev0_h, b_prev0_l, i, h0);
    split_store4(b_h0pre_h, b_h0pre_l, i, ht);
    float4 bR = *(const float4*)&br1[n];
    float4 bF = *(const float4*)&bf1[n];
    float4 p1 = __ldcg((const float4*)&g_prev1[i]);
    float4 rp1 = make_float4(sigmf(s1.x+bR.x)*p1.x, sigmf(s1.y+bR.y)*p1.y,
                             sigmf(s1.z+bR.z)*p1.z, sigmf(s1.w+bR.w)*p1.w);
    split_store4(b_rp1_h, b_rp1_l, i, rp1);
    *(float4*)&g_z1[i] = make_float4(sigmf(s2.x+bF.x), sigmf(s2.y+bF.y),
                                     sigmf(s2.z+bF.z), sigmf(s2.w+bF.w));
}

__device__ __forceinline__ void finB_one(size_t i, int t, int dogates,
                                         const float* bh1, const float* br0, const float* bf0){
    int n = (int)(i & (HID-1));
    float4 s = make_float4(0,0,0,0);
#pragma unroll
    for (int ks = 0; ks < 16; ks++){
        float4 a = __ldcg((const float4*)&g_part[(size_t)ks*BH + i]); V4ADD(s, a);
    }
    float4 bH = *(const float4*)&bh1[n];
    float4 z  = __ldcg((const float4*)&g_z1[i]);
    float4 p1 = __ldcg((const float4*)&g_prev1[i]);
    float4 h1 = make_float4((1.f-z.x)*p1.x + z.x*tanhf(s.x+bH.x),
                            (1.f-z.y)*p1.y + z.y*tanhf(s.y+bH.y),
                            (1.f-z.z)*p1.z + z.z*tanhf(s.z+bH.z),
                            (1.f-z.w)*p1.w + z.w*tanhf(s.w+bH.w));
    *(float4*)&g_prev1[i] = h1;
    split_store4(b_prev1_h, b_prev1_l, i, h1);
    split_store4(gH_hi, gH_lo, (size_t)t*BH + i, h1);
    if (dogates){
        float4 s0 = make_float4(0,0,0,0), s1 = s0;
#pragma unroll
        for (int ks = 0; ks < 8; ks++){
            float4 a = __ldcg((const float4*)&g_part[(size_t)(16+ks)*BH + i]); V4ADD(s0, a);
            float4 b = __ldcg((const float4*)&g_part[(size_t)(24+ks)*BH + i]); V4ADD(s1, b);
        }
        float4 xv = __ldcg((const float4*)&g_Xin[(size_t)(t+1)*BH + i]);
        float4 bR = *(const float4*)&br0[n];
        float4 bF = *(const float4*)&bf0[n];
        float4 p0 = __ldcg((const float4*)&g_prev0[i]);
        float4 rp = make_float4(xv.x+bR.x+s0.x, xv.y+bR.y+s0.y, xv.z+bR.z+s0.z, xv.w+bR.w+s0.w);
        float4 fp = make_float4(xv.x+bF.x+s1.x, xv.y+bF.y+s1.y, xv.z+bF.z+s1.z, xv.w+bF.w+s1.w);
        split_store4(b_r0pre_h, b_r0pre_l, i, rp);
        split_store4(b_f0pre_h, b_f0pre_l, i, fp);
        float4 rpv = make_float4(sigmf(rp.x)*p0.x, sigmf(rp.y)*p0.y, sigmf(rp.z)*p0.z, sigmf(rp.w)*p0.w);
        split_store4(b_rp0_h, b_rp0_l, i, rpv);
        *(float4*)&g_z0[i] = make_float4(sigmf(fp.x), sigmf(fp.y), sigmf(fp.z), sigmf(fp.w));
    }
}

// ---------------- fully-fused persistent kernel ----------------
__global__ void __launch_bounds__(128,3) k_recur(
    const int*   __restrict__ toks, const float* __restrict__ hid,
    const float* __restrict__ emb,  const float* __restrict__ Win,
    const float* __restrict__ Wr1,  const float* __restrict__ Wf1,
    const float* __restrict__ Wh1,  const float* __restrict__ Ur,
    const float* __restrict__ Uf,   const float* __restrict__ Uh,
    const float* __restrict__ br0, const float* __restrict__ bf0,
    const float* __restrict__ bh0, const float* __restrict__ br1,
    const float* __restrict__ bf1, const float* __restrict__ bh1,
    const float* __restrict__ outW,
    const float* __restrict__ outb, float* __restrict__ logits,
    float* __restrict__ hstate)
{
    extern __shared__ __align__(128) char smem[];
    const int b   = blockIdx.x;
    const int tid = threadIdx.x;
    const size_t gtid = (size_t)b*128 + tid;
    const size_t GS   = (size_t)NTOT*128;
    unsigned* xb = (unsigned*)(smem + RECSMEM + 16);   // per-t Xin base snapshot

    // per-invocation bases (previous invocation fully finished -> stable)
    unsigned tdone_base = *(volatile unsigned*)&g_tdone;
    unsigned jobs_base  = *(volatile unsigned*)&g_jobCtr;
    unsigned wr_base    = *(volatile unsigned*)&g_wready;
    if (b < NREC && tid < SEQL) xb[tid] = g_xinT[tid];  // snapshot before any increments

    // ---- common prologue: all conversions, grid-strided over all CTAs ----
    for (size_t i = gtid; i < 2*(size_t)BH; i += GS){
        float v = hid[i];
        if (i < BH){
            g_prev0[i] = v;
            __nv_bfloat16 h = __float2bfloat16_rn(v);
            b_prev0_h[i] = h; b_prev0_l[i] = __float2bfloat16_rn(v - __bfloat162float(h));
        } else {
            size_t j = i - BH;
            g_prev1[j] = v;
            __nv_bfloat16 h = __float2bfloat16_rn(v);
            b_prev1_h[j] = h; b_prev1_l[j] = __float2bfloat16_rn(v - __bfloat162float(h));
        }
    }
    for (size_t i4 = gtid; i4 < (size_t)HH/4; i4 += GS)
        split_store4(gWin_hi, gWin_lo, i4*4, *(const float4*)(Win + i4*4));
    {
        const float* srcs[9] = {Ur, Uf, Uh, Wr1, Ur + HH, Wf1, Uf + HH, Wh1, Uh + HH};
        for (size_t i4 = gtid; i4 < 9*((size_t)HH/4); i4 += GS){
            size_t m = i4 >> 18;
            size_t r = i4 & 262143u;
            split_store4(gRW_hi, gRW_lo, m*HH + r*4, *(const float4*)(srcs[m] + r*4));
        }
    }
    for (size_t i4 = gtid; i4 < (size_t)SEQL*BATCH*EMBD/4; i4 += GS){
        int row  = (int)(i4 >> 8);
        int colq = (int)(i4 & 255);
        int tok  = toks[row];
        float4 v = *(const float4*)(emb + (size_t)tok*EMBD + colq*4);
        v.x *= SQRTE; v.y *= SQRTE; v.z *= SQRTE; v.w *= SQRTE;
        split_store4(gX_hi, gX_lo, i4*4, v);
    }
    ctabar(NTOT);   // conversions visible; xin bases snapshotted

    if (b >= NREC){
        // ---- out-group: Xin tiles t-major (per-t publish), gW split, logits pool ----
        for (unsigned j = (unsigned)(b - NREC); j < XJOBS; j += (unsigned)NOUT){
            unsigned t = j >> 3, nt = j & 7u;
            mma_core64(gX_hi + (size_t)t*BH, gX_lo + (size_t)t*BH,
                       gWin_hi + (size_t)nt*128*HID, gWin_lo + (size_t)nt*128*HID,
                       0, HID, g_Xin, HID, (int)(t*64u), (int)(nt*128u), nullptr);
            __threadfence();
            BARX(1);
            if (tid == 0) atomicAdd(&g_xinT[t], 1u);
        }
        for (size_t i4 = (size_t)(b - NREC)*128 + tid; i4 < (size_t)VOCAB*HID/4; i4 += (size_t)NOUT*128)
            split_store4(gW_hi, gW_lo, i4*4, *(const float4*)(outW + i4*4));
        outbar();
        if (b == NREC && tid == 0){
            __threadfence();
            *(volatile unsigned*)&g_wready = wr_base + 1u;
        }
        out_worker(jobs_base, tdone_base, outb, logits);
        return;
    }

    // ---- recurrence CTA ----
    const bool finT = (tid < 64);
    const size_t item = ((size_t)b*64 + tid)*4;

    // per-t Xin readiness wait (tid0 + broadcast)
    auto wait_xin = [&](int t){
        if (tid == 0){
            unsigned need = xb[t] + 8u;
            while (*(volatile unsigned*)&g_xinT[t] < need) __nanosleep(64);
            __threadfence();
        }
        BARX(1);
    };

    if (b < 128) gates0_body((b>>3)&7, b>>6, b&7);
    ctabar(NREC);
    wait_xin(0);
    if (finT) fin0_one(item, 0, br0, bf0);
    ctabar(NREC);

    for (int t = 0; t < SEQL; t++){
        if (b < 192) mid_job(b);
        ctabar(NREC);
        if (finT) fin_mid_one(item, t, bh0, br1, bf1);
        ctabar(NREC);
        if (b < 128) last_body(b >> 4, b & 15);
        else if (t < SEQL-1){
            int r = b - 128;
            gates0_body((r>>3)&7, r>>6, r&7);
        }
        ctabar(NREC);
        int dg = (t < SEQL-1) ? 1 : 0;
        if (dg) wait_xin(t + 1);
        if (finT) finB_one(item, t, dg, bh1, br0, bf0);
        ctabar(NREC);
        if (b == 0 && tid == 0)
            *(volatile unsigned*)&g_tdone = tdone_base + (unsigned)(t + 1);
    }

    // final hidden-state copy (fused; prev0/prev1 final after last ctabar)
    if (hstate){
        for (size_t i = (size_t)b*128 + tid; i < 2*(size_t)BH; i += (size_t)NREC*128)
            hstate[i] = (i < BH) ? g_prev0[i] : g_prev1[i - BH];
    }

    // join logits pool (guard: gW split complete)
    if (tid == 0){
        while (*(volatile unsigned*)&g_wready < wr_base + 1u) __nanosleep(64);
        __threadfence();
    }
    BARX(1);
    out_worker(jobs_base, tdone_base, outb, logits);
}

// ---------------- launch ----------------
extern "C" void kernel_launch(void* const* d_in, const int* in_sizes, int n_in,
                              void* d_out, int out_size) {
    const int*   toks = (const int*)  d_in[0];
    const float* hid  = (const float*)d_in[1];
    const float* emb  = (const float*)d_in[2];
    const float* Win  = (const float*)d_in[3];
    const float* Wr1  = (const float*)d_in[4];
    const float* Wf1  = (const float*)d_in[5];
    const float* Wh1  = (const float*)d_in[6];
    const float* Ur   = (const float*)d_in[7];
    const float* br   = (const float*)d_in[8];
    const float* Uf   = (const float*)d_in[9];
    const float* bf   = (const float*)d_in[10];
    const float* Uh   = (const float*)d_in[11];
    const float* bh   = (const float*)d_in[12];
    const float* outW = (const float*)d_in[13];
    const float* outb = (const float*)d_in[14];
    float* out = (float*)d_out;

    float* hstate = ((size_t)out_size >= LOGITS_N + 2*(size_t)BH) ? out + LOGITS_N : nullptr;

    cudaFuncSetAttribute(k_recur, cudaFuncAttributeMaxDynamicSharedMemorySize, TOTSMEM);

    // ONE persistent kernel does everything
    k_recur<<<NTOT, 128, TOTSMEM>>>(toks, hid, emb, Win, Wr1, Wf1, Wh1, Ur, Uf, Uh,
                                    br, bf, bh, br + HID, bf + HID, bh + HID,
                                    outW, outb, out, hstate);
}